// round 2
// baseline (speedup 1.0000x reference)
#include <cuda_runtime.h>
#include <math.h>

#define H_DIM 128
#define ED_DIM 16
#define IN1_DIM 273          // 2*H + 1 + ED
#define TILE 64              // edges (or nodes) per block
#define THREADS 256
#define EIN_LD 276           // padded row length for e_in (16B aligned rows)
#define MID_LD 132           // padded row length for 128-wide intermediates
#define NIN_LD 260           // padded row length for node input (256 + pad)

#define MAX_N 20000

__device__ float g_msg[MAX_N * H_DIM];
__device__ float g_coord[MAX_N * 3];

__device__ __forceinline__ float silu_f(float v) {
    return __fdividef(v, 1.0f + __expf(-v));
}

// Tile GEMM: sOut[r][c] = act(sum_k sA[r][k] * W[k][c] + bias[c])
// 64 rows x 128 cols, 256 threads. warp -> 8 rows, lane -> 4 cols.
template <int K, bool DO_SILU>
__device__ __forceinline__ void tile_gemm(const float* __restrict__ sA, int lda,
                                          const float* __restrict__ W,
                                          const float* __restrict__ bias,
                                          float* __restrict__ sOut, int ldo,
                                          int tid) {
    const int warp = tid >> 5;
    const int lane = tid & 31;
    const int r0 = warp * 8;
    const int col0 = lane * 4;

    float acc[8][4];
#pragma unroll
    for (int i = 0; i < 8; i++) {
        acc[i][0] = 0.f; acc[i][1] = 0.f; acc[i][2] = 0.f; acc[i][3] = 0.f;
    }

    constexpr int K4 = K & ~3;
#pragma unroll 4
    for (int k = 0; k < K4; k += 4) {
        const float4 w0 = *(const float4*)(W + (k + 0) * H_DIM + col0);
        const float4 w1 = *(const float4*)(W + (k + 1) * H_DIM + col0);
        const float4 w2 = *(const float4*)(W + (k + 2) * H_DIM + col0);
        const float4 w3 = *(const float4*)(W + (k + 3) * H_DIM + col0);
#pragma unroll
        for (int i = 0; i < 8; i++) {
            const float4 a = *(const float4*)(sA + (r0 + i) * lda + k);
            acc[i][0] = fmaf(a.x, w0.x, fmaf(a.y, w1.x, fmaf(a.z, w2.x, fmaf(a.w, w3.x, acc[i][0]))));
            acc[i][1] = fmaf(a.x, w0.y, fmaf(a.y, w1.y, fmaf(a.z, w2.y, fmaf(a.w, w3.y, acc[i][1]))));
            acc[i][2] = fmaf(a.x, w0.z, fmaf(a.y, w1.z, fmaf(a.z, w2.z, fmaf(a.w, w3.z, acc[i][2]))));
            acc[i][3] = fmaf(a.x, w0.w, fmaf(a.y, w1.w, fmaf(a.z, w2.w, fmaf(a.w, w3.w, acc[i][3]))));
        }
    }
    if (K & 3) {
        for (int k = K4; k < K; k++) {
            const float4 w0 = *(const float4*)(W + k * H_DIM + col0);
#pragma unroll
            for (int i = 0; i < 8; i++) {
                const float a = sA[(r0 + i) * lda + k];
                acc[i][0] = fmaf(a, w0.x, acc[i][0]);
                acc[i][1] = fmaf(a, w0.y, acc[i][1]);
                acc[i][2] = fmaf(a, w0.z, acc[i][2]);
                acc[i][3] = fmaf(a, w0.w, acc[i][3]);
            }
        }
    }

    const float4 b = *(const float4*)(bias + col0);
#pragma unroll
    for (int i = 0; i < 8; i++) {
        float4 o;
        o.x = acc[i][0] + b.x;
        o.y = acc[i][1] + b.y;
        o.z = acc[i][2] + b.z;
        o.w = acc[i][3] + b.w;
        if (DO_SILU) {
            o.x = silu_f(o.x); o.y = silu_f(o.y); o.z = silu_f(o.z); o.w = silu_f(o.w);
        }
        *(float4*)(sOut + (r0 + i) * ldo + col0) = o;
    }
}

// ---------------------------------------------------------------------------
// Edge kernel: per 64-edge tile, compute m_ij + coord weight, scatter-add.
// ---------------------------------------------------------------------------
__global__ void __launch_bounds__(THREADS, 1)
egnn_edge(const float* __restrict__ h, const float* __restrict__ x,
          const int* __restrict__ ei, const float* __restrict__ ea,
          const float* __restrict__ We1, const float* __restrict__ be1,
          const float* __restrict__ We2, const float* __restrict__ be2,
          const float* __restrict__ Wx1, const float* __restrict__ bx1,
          const float* __restrict__ Wx2, const float* __restrict__ bx2,
          int E_) {
    extern __shared__ float sm[];
    float* s_ein  = sm;                       // TILE * EIN_LD
    float* s_m1   = s_ein + TILE * EIN_LD;    // TILE * MID_LD
    float* s_m    = s_m1 + TILE * MID_LD;     // TILE * MID_LD  (m_ij)
    float* s_w    = s_m + TILE * MID_LD;      // TILE
    float* s_diff = s_w + TILE;               // TILE * 3
    int*   s_dst  = (int*)(s_diff + TILE * 3);// TILE

    const int tid = threadIdx.x;
    const int warp = tid >> 5;
    const int lane = tid & 31;
    const long eBaseG = (long)blockIdx.x * TILE;

    // ---- Phase A: assemble e_in = [h[src], h[dst], dist2/100, edge_attr]
#pragma unroll
    for (int i = 0; i < 8; i++) {
        const int e = warp * 8 + i;
        const long eg = eBaseG + e;
        float* row = s_ein + e * EIN_LD;
        if (eg < E_) {
            const int src = ei[eg];
            const int dst = ei[(long)E_ + eg];
            const float4 hs = *(const float4*)(h + (long)src * H_DIM + lane * 4);
            *(float4*)(row + lane * 4) = hs;
            const float4 hd = *(const float4*)(h + (long)dst * H_DIM + lane * 4);
            *(float4*)(row + 128 + lane * 4) = hd;
            if (lane < 16) row[257 + lane] = ea[eg * ED_DIM + lane];
            if (lane == 0) {
                const float dx = x[src * 3 + 0] - x[dst * 3 + 0];
                const float dy = x[src * 3 + 1] - x[dst * 3 + 1];
                const float dz = x[src * 3 + 2] - x[dst * 3 + 2];
                s_diff[e * 3 + 0] = dx;
                s_diff[e * 3 + 1] = dy;
                s_diff[e * 3 + 2] = dz;
                row[256] = (dx * dx + dy * dy + dz * dz) * 0.01f;
                s_dst[e] = dst;
            }
        } else {
            *(float4*)(row + lane * 4) = make_float4(0.f, 0.f, 0.f, 0.f);
            *(float4*)(row + 128 + lane * 4) = make_float4(0.f, 0.f, 0.f, 0.f);
            if (lane < 17) row[256 + lane] = 0.f;
            if (lane == 0) {
                s_dst[e] = 0;
                s_diff[e * 3 + 0] = s_diff[e * 3 + 1] = s_diff[e * 3 + 2] = 0.f;
            }
        }
    }
    __syncthreads();

    // ---- GEMM 1: m1 = silu(e_in @ We1 + be1)
    tile_gemm<IN1_DIM, true>(s_ein, EIN_LD, We1, be1, s_m1, MID_LD, tid);
    __syncthreads();
    // ---- GEMM 2: m_ij = silu(m1 @ We2 + be2)
    tile_gemm<H_DIM, true>(s_m1, MID_LD, We2, be2, s_m, MID_LD, tid);
    __syncthreads();
    // ---- GEMM 3: t = silu(m_ij @ Wx1 + bx1) -> reuse s_ein
    tile_gemm<H_DIM, true>(s_m, MID_LD, Wx1, bx1, s_ein, MID_LD, tid);
    __syncthreads();

    // ---- GEMM 4: w_e = tanh(t @ Wx2 + bx2) -- per-edge dot of length 128
    const float bx = bx2[0];
#pragma unroll
    for (int i = 0; i < 8; i++) {
        const int e = warp * 8 + i;
        const float* t = s_ein + e * MID_LD;
        float p = t[lane] * Wx2[lane] + t[lane + 32] * Wx2[lane + 32] +
                  t[lane + 64] * Wx2[lane + 64] + t[lane + 96] * Wx2[lane + 96];
#pragma unroll
        for (int o = 16; o > 0; o >>= 1) p += __shfl_xor_sync(0xffffffffu, p, o);
        if (lane == 0) s_w[e] = tanhf(p + bx);
    }
    __syncthreads();

    // ---- Scatter m_ij into g_msg (atomic add, result unused -> RED)
    const int col0 = lane * 4;
#pragma unroll
    for (int i = 0; i < 8; i++) {
        const int e = warp * 8 + i;
        const long eg = eBaseG + e;
        if (eg < E_) {
            float* dp = g_msg + (long)s_dst[e] * H_DIM + col0;
            const float* mp = s_m + e * MID_LD + col0;
            atomicAdd(dp + 0, mp[0]);
            atomicAdd(dp + 1, mp[1]);
            atomicAdd(dp + 2, mp[2]);
            atomicAdd(dp + 3, mp[3]);
        }
    }
    // ---- Scatter coord contributions
    if (tid < TILE * 3) {
        const int e = tid / 3;
        const int c = tid - e * 3;
        const long eg = eBaseG + e;
        if (eg < E_) {
            atomicAdd(&g_coord[(long)s_dst[e] * 3 + c], s_diff[e * 3 + c] * s_w[e]);
        }
    }
}

// ---------------------------------------------------------------------------
// Node kernel: h_new = h + silu([h, msg] @ Wh1 + bh1) @ Wh2 + bh2
//              x_new = x + coord_agg * (~fixed)
// ---------------------------------------------------------------------------
__global__ void __launch_bounds__(THREADS, 1)
egnn_node(const float* __restrict__ h, const float* __restrict__ x,
          const int* __restrict__ fixedm,
          const float* __restrict__ Wh1, const float* __restrict__ bh1,
          const float* __restrict__ Wh2, const float* __restrict__ bh2,
          float* __restrict__ out_h, float* __restrict__ out_x, int N_) {
    extern __shared__ float sm[];
    float* s_in = sm;                    // TILE * NIN_LD
    float* s_u  = s_in + TILE * NIN_LD;  // TILE * MID_LD

    const int tid = threadIdx.x;
    const int warp = tid >> 5;
    const int lane = tid & 31;
    const int nBase = blockIdx.x * TILE;

    // ---- Assemble [h, msg_agg]
#pragma unroll
    for (int i = 0; i < 8; i++) {
        const int ln = warp * 8 + i;
        const int node = nBase + ln;
        float* row = s_in + ln * NIN_LD;
        if (node < N_) {
            *(float4*)(row + lane * 4) =
                *(const float4*)(h + (long)node * H_DIM + lane * 4);
            *(float4*)(row + 128 + lane * 4) =
                *(const float4*)(g_msg + (long)node * H_DIM + lane * 4);
        } else {
            *(float4*)(row + lane * 4) = make_float4(0.f, 0.f, 0.f, 0.f);
            *(float4*)(row + 128 + lane * 4) = make_float4(0.f, 0.f, 0.f, 0.f);
        }
    }
    __syncthreads();

    tile_gemm<2 * H_DIM, true>(s_in, NIN_LD, Wh1, bh1, s_u, MID_LD, tid);
    __syncthreads();
    // second GEMM writes into s_in region (no longer read)
    tile_gemm<H_DIM, false>(s_u, MID_LD, Wh2, bh2, s_in, MID_LD, tid);
    __syncthreads();

    // ---- residual + store h_new
#pragma unroll
    for (int i = 0; i < 8; i++) {
        const int ln = warp * 8 + i;
        const int node = nBase + ln;
        if (node < N_) {
            float4 o = *(const float4*)(s_in + ln * MID_LD + lane * 4);
            const float4 hh = *(const float4*)(h + (long)node * H_DIM + lane * 4);
            o.x += hh.x; o.y += hh.y; o.z += hh.z; o.w += hh.w;
            *(float4*)(out_h + (long)node * H_DIM + lane * 4) = o;
        }
    }
    // ---- x_new
    if (tid < TILE * 3) {
        const int li = tid / 3;
        const int c = tid - li * 3;
        const int node = nBase + li;
        if (node < N_) {
            const float add = fixedm[node] ? 0.f : g_coord[node * 3 + c];
            out_x[node * 3 + c] = x[node * 3 + c] + add;
        }
    }
}

extern "C" void kernel_launch(void* const* d_in, const int* in_sizes, int n_in,
                              void* d_out, int out_size) {
    const float* h   = (const float*)d_in[0];
    const float* x   = (const float*)d_in[1];
    const int* ei    = (const int*)d_in[2];
    const float* ea  = (const float*)d_in[3];
    const int* fixedm = (const int*)d_in[4];
    const float* We1 = (const float*)d_in[5];
    const float* be1 = (const float*)d_in[6];
    const float* We2 = (const float*)d_in[7];
    const float* be2 = (const float*)d_in[8];
    const float* Wx1 = (const float*)d_in[9];
    const float* bx1 = (const float*)d_in[10];
    const float* Wx2 = (const float*)d_in[11];
    const float* bx2 = (const float*)d_in[12];
    const float* Wh1 = (const float*)d_in[13];
    const float* bh1 = (const float*)d_in[14];
    const float* Wh2 = (const float*)d_in[15];
    const float* bh2 = (const float*)d_in[16];

    const int N_ = in_sizes[0] / H_DIM;
    const int E_ = in_sizes[3] / ED_DIM;

    float* out_h = (float*)d_out;
    float* out_x = out_h + (long)N_ * H_DIM;

    void* pmsg = nullptr;
    void* pcoord = nullptr;
    cudaGetSymbolAddress(&pmsg, g_msg);
    cudaGetSymbolAddress(&pcoord, g_coord);
    cudaMemsetAsync(pmsg, 0, (size_t)N_ * H_DIM * sizeof(float));
    cudaMemsetAsync(pcoord, 0, (size_t)N_ * 3 * sizeof(float));

    const int edgeSmem =
        (TILE * EIN_LD + 2 * TILE * MID_LD + TILE + TILE * 3) * 4 + TILE * 4;
    const int nodeSmem = (TILE * NIN_LD + TILE * MID_LD) * 4;

    cudaFuncSetAttribute(egnn_edge, cudaFuncAttributeMaxDynamicSharedMemorySize,
                         edgeSmem);
    cudaFuncSetAttribute(egnn_node, cudaFuncAttributeMaxDynamicSharedMemorySize,
                         nodeSmem);

    const int eBlocks = (E_ + TILE - 1) / TILE;
    egnn_edge<<<eBlocks, THREADS, edgeSmem>>>(h, x, ei, ea, We1, be1, We2, be2,
                                              Wx1, bx1, Wx2, bx2, E_);

    const int nBlocks = (N_ + TILE - 1) / TILE;
    egnn_node<<<nBlocks, THREADS, nodeSmem>>>(h, x, fixedm, Wh1, bh1, Wh2, bh2,
                                              out_h, out_x, N_);
}

// round 4
// speedup vs baseline: 1.8990x; 1.8990x over previous
#include <cuda_runtime.h>
#include <math.h>
#include <stdint.h>

#define H_DIM 128
#define ED_DIM 16
#define ETILE 128
#define THREADS 256
#define MAX_N 20000
#define LDA 132            // row pitch (floats) for A/B smem; 132 % 32 == 4 -> conflict-free

// ---------------- device scratch ----------------
__device__ float g_msg[MAX_N * H_DIM];
__device__ float g_coord[MAX_N * 3];
// Pre-transposed tf32 weight images Wt[n][k], 5 chunks of [128][LDA]:
// 0,1,2: We1^T k-chunks (128,128,24used)  3: We2^T  4: Wx1^T
__device__ float g_B[5 * 128 * LDA];

__device__ __forceinline__ float totf32(float f) {
    uint32_t u;
    asm("cvt.rna.tf32.f32 %0, %1;" : "=r"(u) : "f"(f));
    return __uint_as_float(u);
}
__device__ __forceinline__ float silu_f(float v) {
    return __fdividef(v, 1.0f + __expf(-v));
}

// ---------------- weight prep ----------------
__global__ void prep_w(const float* __restrict__ We1, const float* __restrict__ We2,
                       const float* __restrict__ Wx1) {
    const int idx = blockIdx.x * 256 + threadIdx.x;
    if (idx >= 5 * 128 * LDA) return;
    const int chunk = idx / (128 * LDA);
    const int rem = idx % (128 * LDA);
    const int n = rem / LDA, k = rem % LDA;
    float v = 0.f;
    if (chunk == 0)      { if (k < 128) v = We1[k * 128 + n]; }
    else if (chunk == 1) { if (k < 128) v = We1[(128 + k) * 128 + n]; }
    else if (chunk == 2) { if (k <= 16) v = We1[(256 + k) * 128 + n]; }  // k=0:dist row, k=1..16: ea rows
    else if (chunk == 3) { if (k < 128) v = We2[k * 128 + n]; }
    else                 { if (k < 128) v = Wx1[k * 128 + n]; }
    g_B[idx] = totf32(v);
}

// ---------------- mma.sync helper ----------------
__device__ __forceinline__ void mma_tf32(float* d, const uint32_t* a, const uint32_t* b) {
    asm volatile(
        "mma.sync.aligned.m16n8k8.row.col.f32.tf32.tf32.f32 "
        "{%0,%1,%2,%3}, {%4,%5,%6,%7}, {%8,%9}, {%0,%1,%2,%3};"
        : "+f"(d[0]), "+f"(d[1]), "+f"(d[2]), "+f"(d[3])
        : "r"(a[0]), "r"(a[1]), "r"(a[2]), "r"(a[3]), "r"(b[0]), "r"(b[1]));
}

// smem layout (float offsets)
#define OFF_A    0
#define OFF_B    16896
#define OFF_BIAS 33792
#define OFF_WX2  33920
#define OFF_DIFF 34048   // 384
#define OFF_DST  34432   // 128 (int)
#define OFF_PART 34560   // 256 (also holds dist during GEMM1)
#define SMEM_FLOATS 34816

// ---------------------------------------------------------------------------
// Edge kernel: tf32 mma.sync GEMM chain, register accumulators, fused scatter
// ---------------------------------------------------------------------------
__global__ void __launch_bounds__(THREADS, 1)
egnn_edge_mma(const float* __restrict__ h, const float* __restrict__ x,
              const int* __restrict__ ei, const float* __restrict__ ea,
              const float* __restrict__ be1, const float* __restrict__ be2,
              const float* __restrict__ bx1, const float* __restrict__ Wx2,
              const float* __restrict__ bx2, int E_) {
    extern __shared__ float sm[];
    float* sA    = sm + OFF_A;     // [128][LDA] activations (tf32 bits)
    float* sB    = sm + OFF_B;     // [128][LDA] weights Wt[n][k]
    float* sBIAS = sm + OFF_BIAS;
    float* sWX2  = sm + OFF_WX2;
    float* sDIFF = sm + OFF_DIFF;
    int*   sDST  = (int*)(sm + OFF_DST);
    float* sPART = sm + OFF_PART;

    const int tid = threadIdx.x, warp = tid >> 5, lane = tid & 31;
    const int g = lane >> 2, c = lane & 3;
    const int warpM = warp >> 1, warpN = warp & 1;
    const int rb = warpM * 32, cb = warpN * 64;
    const long base = (long)blockIdx.x * ETILE;

    float acc[2][8][4];
#pragma unroll
    for (int mt = 0; mt < 2; mt++)
#pragma unroll
        for (int nt = 0; nt < 8; nt++)
#pragma unroll
            for (int j = 0; j < 4; j++) acc[mt][nt][j] = 0.f;

    // ================= GEMM 1: K=273 in 3 chunks =================
    for (int chunk = 0; chunk < 3; chunk++) {
        // ---- load A chunk
        if (chunk < 2) {
#pragma unroll
            for (int i = 0; i < 16; i++) {
                const int r = warp * 16 + i;
                const long eg = base + r;
                const int nd = (eg < E_) ? ei[(long)chunk * E_ + eg] : 0;
                float4 v = *(const float4*)(h + (long)nd * H_DIM + lane * 4);
                v.x = totf32(v.x); v.y = totf32(v.y);
                v.z = totf32(v.z); v.w = totf32(v.w);
                *(float4*)(sA + r * LDA + lane * 4) = v;
                if (chunk == 0 && lane == 0) {
                    const int dn = (eg < E_) ? ei[(long)E_ + eg] : 0;
                    sDST[r] = dn;
                    const float dx = x[nd * 3 + 0] - x[dn * 3 + 0];
                    const float dy = x[nd * 3 + 1] - x[dn * 3 + 1];
                    const float dz = x[nd * 3 + 2] - x[dn * 3 + 2];
                    sDIFF[r * 3 + 0] = dx; sDIFF[r * 3 + 1] = dy; sDIFF[r * 3 + 2] = dz;
                    sPART[r] = (dx * dx + dy * dy + dz * dz) * 0.01f;  // dist (temp)
                }
            }
        } else {
            for (int idx = tid; idx < 128 * 24; idx += THREADS) {
                const int r = idx / 24, kl = idx - r * 24;
                const long eg = base + r;
                float v = 0.f;
                if (kl == 0) v = sPART[r];
                else if (kl <= 16 && eg < E_) v = ea[eg * ED_DIM + kl - 1];
                sA[r * LDA + kl] = totf32(v);
            }
            if (tid < 128) sBIAS[tid] = be1[tid];
        }
        // ---- load B chunk
        {
            const float4* gB = (const float4*)(g_B + chunk * 128 * LDA);
            float4* dB = (float4*)sB;
            for (int i = tid; i < 128 * LDA / 4; i += THREADS) dB[i] = gB[i];
        }
        __syncthreads();
        // ---- mma over K-steps
        const int nst = (chunk == 2) ? 3 : 16;
        for (int s = 0; s < nst; s++) {
            const int k0 = s * 8;
            uint32_t a[2][4], b[8][2];
#pragma unroll
            for (int mt = 0; mt < 2; mt++) {
                const int r0 = rb + mt * 16 + g;
                a[mt][0] = __float_as_uint(sA[r0 * LDA + k0 + c]);
                a[mt][1] = __float_as_uint(sA[(r0 + 8) * LDA + k0 + c]);
                a[mt][2] = __float_as_uint(sA[r0 * LDA + k0 + c + 4]);
                a[mt][3] = __float_as_uint(sA[(r0 + 8) * LDA + k0 + c + 4]);
            }
#pragma unroll
            for (int nt = 0; nt < 8; nt++) {
                const int n = cb + nt * 8 + g;
                b[nt][0] = __float_as_uint(sB[n * LDA + k0 + c]);
                b[nt][1] = __float_as_uint(sB[n * LDA + k0 + c + 4]);
            }
#pragma unroll
            for (int mt = 0; mt < 2; mt++)
#pragma unroll
                for (int nt = 0; nt < 8; nt++) mma_tf32(acc[mt][nt], a[mt], b[nt]);
        }
        __syncthreads();
    }

    // ======== Epilogue 1: m1 = silu(acc + be1) -> sA (tf32), reset acc ========
#pragma unroll
    for (int mt = 0; mt < 2; mt++) {
        const int r0 = rb + mt * 16 + g;
#pragma unroll
        for (int nt = 0; nt < 8; nt++) {
            const int col = cb + nt * 8 + 2 * c;
            float* a4 = acc[mt][nt];
            float2 lo, hi;
            lo.x = totf32(silu_f(a4[0] + sBIAS[col]));
            lo.y = totf32(silu_f(a4[1] + sBIAS[col + 1]));
            hi.x = totf32(silu_f(a4[2] + sBIAS[col]));
            hi.y = totf32(silu_f(a4[3] + sBIAS[col + 1]));
            *(float2*)(sA + r0 * LDA + col) = lo;
            *(float2*)(sA + (r0 + 8) * LDA + col) = hi;
            a4[0] = a4[1] = a4[2] = a4[3] = 0.f;
        }
    }
    __syncthreads();

    // ================= GEMM 2: m = silu(m1 @ We2 + be2) =================
    {
        const float4* gB = (const float4*)(g_B + 3 * 128 * LDA);
        float4* dB = (float4*)sB;
        for (int i = tid; i < 128 * LDA / 4; i += THREADS) dB[i] = gB[i];
        if (tid < 128) sBIAS[tid] = be2[tid];
        __syncthreads();
        for (int s = 0; s < 16; s++) {
            const int k0 = s * 8;
            uint32_t a[2][4], b[8][2];
#pragma unroll
            for (int mt = 0; mt < 2; mt++) {
                const int r0 = rb + mt * 16 + g;
                a[mt][0] = __float_as_uint(sA[r0 * LDA + k0 + c]);
                a[mt][1] = __float_as_uint(sA[(r0 + 8) * LDA + k0 + c]);
                a[mt][2] = __float_as_uint(sA[r0 * LDA + k0 + c + 4]);
                a[mt][3] = __float_as_uint(sA[(r0 + 8) * LDA + k0 + c + 4]);
            }
#pragma unroll
            for (int nt = 0; nt < 8; nt++) {
                const int n = cb + nt * 8 + g;
                b[nt][0] = __float_as_uint(sB[n * LDA + k0 + c]);
                b[nt][1] = __float_as_uint(sB[n * LDA + k0 + c + 4]);
            }
#pragma unroll
            for (int mt = 0; mt < 2; mt++)
#pragma unroll
                for (int nt = 0; nt < 8; nt++) mma_tf32(acc[mt][nt], a[mt], b[nt]);
        }
        __syncthreads();
    }

    // ==== Epilogue 2: m_ij = silu(acc+be2); scatter to g_msg; -> sA; reset ====
#pragma unroll
    for (int mt = 0; mt < 2; mt++) {
        const int r0 = rb + mt * 16 + g;
        const int r1 = r0 + 8;
        const int dn0 = sDST[r0], dn1 = sDST[r1];
        const bool v0 = (base + r0) < E_, v1 = (base + r1) < E_;
        float* mp0 = g_msg + (long)dn0 * H_DIM;
        float* mp1 = g_msg + (long)dn1 * H_DIM;
#pragma unroll
        for (int nt = 0; nt < 8; nt++) {
            const int col = cb + nt * 8 + 2 * c;
            float* a4 = acc[mt][nt];
            const float m00 = silu_f(a4[0] + sBIAS[col]);
            const float m01 = silu_f(a4[1] + sBIAS[col + 1]);
            const float m10 = silu_f(a4[2] + sBIAS[col]);
            const float m11 = silu_f(a4[3] + sBIAS[col + 1]);
            if (v0) { atomicAdd(mp0 + col, m00); atomicAdd(mp0 + col + 1, m01); }
            if (v1) { atomicAdd(mp1 + col, m10); atomicAdd(mp1 + col + 1, m11); }
            float2 lo, hi;
            lo.x = totf32(m00); lo.y = totf32(m01);
            hi.x = totf32(m10); hi.y = totf32(m11);
            *(float2*)(sA + r0 * LDA + col) = lo;
            *(float2*)(sA + r1 * LDA + col) = hi;
            a4[0] = a4[1] = a4[2] = a4[3] = 0.f;
        }
    }
    __syncthreads();

    // ================= GEMM 3: t = silu(m @ Wx1 + bx1) =================
    {
        const float4* gB = (const float4*)(g_B + 4 * 128 * LDA);
        float4* dB = (float4*)sB;
        for (int i = tid; i < 128 * LDA / 4; i += THREADS) dB[i] = gB[i];
        if (tid < 128) { sBIAS[tid] = bx1[tid]; sWX2[tid] = Wx2[tid]; }
        __syncthreads();
        for (int s = 0; s < 16; s++) {
            const int k0 = s * 8;
            uint32_t a[2][4], b[8][2];
#pragma unroll
            for (int mt = 0; mt < 2; mt++) {
                const int r0 = rb + mt * 16 + g;
                a[mt][0] = __float_as_uint(sA[r0 * LDA + k0 + c]);
                a[mt][1] = __float_as_uint(sA[(r0 + 8) * LDA + k0 + c]);
                a[mt][2] = __float_as_uint(sA[r0 * LDA + k0 + c + 4]);
                a[mt][3] = __float_as_uint(sA[(r0 + 8) * LDA + k0 + c + 4]);
            }
#pragma unroll
            for (int nt = 0; nt < 8; nt++) {
                const int n = cb + nt * 8 + g;
                b[nt][0] = __float_as_uint(sB[n * LDA + k0 + c]);
                b[nt][1] = __float_as_uint(sB[n * LDA + k0 + c + 4]);
            }
#pragma unroll
            for (int mt = 0; mt < 2; mt++)
#pragma unroll
                for (int nt = 0; nt < 8; nt++) mma_tf32(acc[mt][nt], a[mt], b[nt]);
        }
        __syncthreads();
    }

    // ===== Epilogue 3: silu, dot with Wx2, reduce, tanh, coord scatter =====
    {
        float p[4] = {0.f, 0.f, 0.f, 0.f};   // [mt*2 + rowhalf]
#pragma unroll
        for (int mt = 0; mt < 2; mt++) {
#pragma unroll
            for (int nt = 0; nt < 8; nt++) {
                const int col = cb + nt * 8 + 2 * c;
                const float w0 = sWX2[col], w1 = sWX2[col + 1];
                float* a4 = acc[mt][nt];
                p[mt * 2 + 0] += silu_f(a4[0] + sBIAS[col]) * w0 + silu_f(a4[1] + sBIAS[col + 1]) * w1;
                p[mt * 2 + 1] += silu_f(a4[2] + sBIAS[col]) * w0 + silu_f(a4[3] + sBIAS[col + 1]) * w1;
            }
        }
#pragma unroll
        for (int off = 1; off <= 2; off <<= 1) {
#pragma unroll
            for (int j = 0; j < 4; j++) p[j] += __shfl_xor_sync(0xffffffffu, p[j], off);
        }
        if (c == 0) {
#pragma unroll
            for (int mt = 0; mt < 2; mt++) {
                sPART[(rb + mt * 16 + g) + warpN * 128] = p[mt * 2 + 0];
                sPART[(rb + mt * 16 + g + 8) + warpN * 128] = p[mt * 2 + 1];
            }
        }
    }
    __syncthreads();
    if (tid < 128) {
        const long eg = base + tid;
        if (eg < E_) {
            const float w = tanhf(sPART[tid] + sPART[tid + 128] + bx2[0]);
            const int dn = sDST[tid];
            atomicAdd(&g_coord[dn * 3 + 0], sDIFF[tid * 3 + 0] * w);
            atomicAdd(&g_coord[dn * 3 + 1], sDIFF[tid * 3 + 1] * w);
            atomicAdd(&g_coord[dn * 3 + 2], sDIFF[tid * 3 + 2] * w);
        }
    }
}

// ---------------------------------------------------------------------------
// Node kernel (fp32, ~70us)
// ---------------------------------------------------------------------------
#define TILE 64
#define MID_LD 132
#define NIN_LD 260

template <int K, bool DO_SILU>
__device__ __forceinline__ void tile_gemm(const float* __restrict__ sA, int lda,
                                          const float* __restrict__ W,
                                          const float* __restrict__ bias,
                                          float* __restrict__ sOut, int ldo,
                                          int tid) {
    const int warp = tid >> 5;
    const int lane = tid & 31;
    const int r0 = warp * 8;
    const int col0 = lane * 4;

    float acc[8][4];
#pragma unroll
    for (int i = 0; i < 8; i++) {
        acc[i][0] = 0.f; acc[i][1] = 0.f; acc[i][2] = 0.f; acc[i][3] = 0.f;
    }
#pragma unroll 4
    for (int k = 0; k < K; k += 4) {
        const float4 w0 = *(const float4*)(W + (k + 0) * H_DIM + col0);
        const float4 w1 = *(const float4*)(W + (k + 1) * H_DIM + col0);
        const float4 w2 = *(const float4*)(W + (k + 2) * H_DIM + col0);
        const float4 w3 = *(const float4*)(W + (k + 3) * H_DIM + col0);
#pragma unroll
        for (int i = 0; i < 8; i++) {
            const float4 a = *(const float4*)(sA + (r0 + i) * lda + k);
            acc[i][0] = fmaf(a.x, w0.x, fmaf(a.y, w1.x, fmaf(a.z, w2.x, fmaf(a.w, w3.x, acc[i][0]))));
            acc[i][1] = fmaf(a.x, w0.y, fmaf(a.y, w1.y, fmaf(a.z, w2.y, fmaf(a.w, w3.y, acc[i][1]))));
            acc[i][2] = fmaf(a.x, w0.z, fmaf(a.y, w1.z, fmaf(a.z, w2.z, fmaf(a.w, w3.z, acc[i][2]))));
            acc[i][3] = fmaf(a.x, w0.w, fmaf(a.y, w1.w, fmaf(a.z, w2.w, fmaf(a.w, w3.w, acc[i][3]))));
        }
    }
    const float4 b = *(const float4*)(bias + col0);
#pragma unroll
    for (int i = 0; i < 8; i++) {
        float4 o;
        o.x = acc[i][0] + b.x; o.y = acc[i][1] + b.y;
        o.z = acc[i][2] + b.z; o.w = acc[i][3] + b.w;
        if (DO_SILU) {
            o.x = silu_f(o.x); o.y = silu_f(o.y);
            o.z = silu_f(o.z); o.w = silu_f(o.w);
        }
        *(float4*)(sOut + (r0 + i) * ldo + col0) = o;
    }
}

__global__ void __launch_bounds__(THREADS, 1)
egnn_node(const float* __restrict__ h, const float* __restrict__ x,
          const int* __restrict__ fixedm,
          const float* __restrict__ Wh1, const float* __restrict__ bh1,
          const float* __restrict__ Wh2, const float* __restrict__ bh2,
          float* __restrict__ out_h, float* __restrict__ out_x, int N_) {
    extern __shared__ float sm[];
    float* s_in = sm;
    float* s_u  = s_in + TILE * NIN_LD;

    const int tid = threadIdx.x;
    const int warp = tid >> 5;
    const int lane = tid & 31;
    const int nBase = blockIdx.x * TILE;

#pragma unroll
    for (int i = 0; i < 8; i++) {
        const int ln = warp * 8 + i;
        const int node = nBase + ln;
        float* row = s_in + ln * NIN_LD;
        if (node < N_) {
            *(float4*)(row + lane * 4) = *(const float4*)(h + (long)node * H_DIM + lane * 4);
            *(float4*)(row + 128 + lane * 4) = *(const float4*)(g_msg + (long)node * H_DIM + lane * 4);
        } else {
            *(float4*)(row + lane * 4) = make_float4(0.f, 0.f, 0.f, 0.f);
            *(float4*)(row + 128 + lane * 4) = make_float4(0.f, 0.f, 0.f, 0.f);
        }
    }
    __syncthreads();

    tile_gemm<2 * H_DIM, true>(s_in, NIN_LD, Wh1, bh1, s_u, MID_LD, tid);
    __syncthreads();
    tile_gemm<H_DIM, false>(s_u, MID_LD, Wh2, bh2, s_in, MID_LD, tid);
    __syncthreads();

#pragma unroll
    for (int i = 0; i < 8; i++) {
        const int ln = warp * 8 + i;
        const int node = nBase + ln;
        if (node < N_) {
            float4 o = *(const float4*)(s_in + ln * MID_LD + lane * 4);
            const float4 hh = *(const float4*)(h + (long)node * H_DIM + lane * 4);
            o.x += hh.x; o.y += hh.y; o.z += hh.z; o.w += hh.w;
            *(float4*)(out_h + (long)node * H_DIM + lane * 4) = o;
        }
    }
    if (tid < TILE * 3) {
        const int li = tid / 3;
        const int c = tid - li * 3;
        const int node = nBase + li;
        if (node < N_) {
            const float add = fixedm[node] ? 0.f : g_coord[node * 3 + c];
            out_x[node * 3 + c] = x[node * 3 + c] + add;
        }
    }
}

// ---------------------------------------------------------------------------
extern "C" void kernel_launch(void* const* d_in, const int* in_sizes, int n_in,
                              void* d_out, int out_size) {
    const float* h   = (const float*)d_in[0];
    const float* x   = (const float*)d_in[1];
    const int* ei    = (const int*)d_in[2];
    const float* ea  = (const float*)d_in[3];
    const int* fixedm = (const int*)d_in[4];
    const float* We1 = (const float*)d_in[5];
    const float* be1 = (const float*)d_in[6];
    const float* We2 = (const float*)d_in[7];
    const float* be2 = (const float*)d_in[8];
    const float* Wx1 = (const float*)d_in[9];
    const float* bx1 = (const float*)d_in[10];
    const float* Wx2 = (const float*)d_in[11];
    const float* bx2 = (const float*)d_in[12];
    const float* Wh1 = (const float*)d_in[13];
    const float* bh1 = (const float*)d_in[14];
    const float* Wh2 = (const float*)d_in[15];
    const float* bh2 = (const float*)d_in[16];

    const int N_ = in_sizes[0] / H_DIM;
    const int E_ = in_sizes[3] / ED_DIM;

    float* out_h = (float*)d_out;
    float* out_x = out_h + (long)N_ * H_DIM;

    void* pmsg = nullptr; void* pcoord = nullptr;
    cudaGetSymbolAddress(&pmsg, g_msg);
    cudaGetSymbolAddress(&pcoord, g_coord);
    cudaMemsetAsync(pmsg, 0, (size_t)N_ * H_DIM * sizeof(float));
    cudaMemsetAsync(pcoord, 0, (size_t)N_ * 3 * sizeof(float));

    prep_w<<<(5 * 128 * LDA + 255) / 256, 256>>>(We1, We2, Wx1);

    const int edgeSmem = SMEM_FLOATS * 4;
    cudaFuncSetAttribute(egnn_edge_mma, cudaFuncAttributeMaxDynamicSharedMemorySize, edgeSmem);
    const int eBlocks = (E_ + ETILE - 1) / ETILE;
    egnn_edge_mma<<<eBlocks, THREADS, edgeSmem>>>(h, x, ei, ea, be1, be2, bx1,
                                                  Wx2, bx2, E_);

    const int nodeSmem = (TILE * NIN_LD + TILE * MID_LD) * 4;
    cudaFuncSetAttribute(egnn_node, cudaFuncAttributeMaxDynamicSharedMemorySize, nodeSmem);
    const int nBlocks = (N_ + TILE - 1) / TILE;
    egnn_node<<<nBlocks, THREADS, nodeSmem>>>(h, x, fixedm, Wh1, bh1, Wh2, bh2,
                                              out_h, out_x, N_);
}

// round 5
// speedup vs baseline: 3.7490x; 1.9742x over previous
#include <cuda_runtime.h>
#include <cuda_fp16.h>
#include <math.h>
#include <stdint.h>

#define H_DIM 128
#define ED_DIM 16
#define ETILE 128
#define THREADS 256
#define MAX_N 20000
#define LDH 136            // half-element pitch; 68 words % 32 == 4 -> conflict-free

// ---------------- device scratch ----------------
__device__ float g_msg[MAX_N * H_DIM];
__device__ float g_coord[MAX_N * 3];
// fp16 transposed weight images Wt[n][k], 5 chunks of [128][LDH]:
// 0,1: We1^T k 0..127 / 128..255   2: We1^T k 256..272 (pad 32)
// 3: We2^T   4: Wx1^T
__device__ __half g_B[5 * 128 * LDH];

__device__ __forceinline__ float silu_f(float v) {
    return __fdividef(v, 1.0f + __expf(-v));
}

// ---------------- weight prep ----------------
__global__ void prep_w(const float* __restrict__ We1, const float* __restrict__ We2,
                       const float* __restrict__ Wx1) {
    const int idx = blockIdx.x * 256 + threadIdx.x;
    if (idx >= 5 * 128 * LDH) return;
    const int chunk = idx / (128 * LDH);
    const int rem = idx % (128 * LDH);
    const int n = rem / LDH, k = rem % LDH;
    float v = 0.f;
    if (chunk == 0)      { if (k < 128) v = We1[k * 128 + n]; }
    else if (chunk == 1) { if (k < 128) v = We1[(128 + k) * 128 + n]; }
    else if (chunk == 2) { if (k <= 16) v = We1[(256 + k) * 128 + n]; }
    else if (chunk == 3) { if (k < 128) v = We2[k * 128 + n]; }
    else                 { if (k < 128) v = Wx1[k * 128 + n]; }
    g_B[idx] = __float2half_rn(v);
}

// ---------------- mma helper ----------------
__device__ __forceinline__ void mma_f16(float* d, const uint32_t* a, const uint32_t* b) {
    asm volatile(
        "mma.sync.aligned.m16n8k16.row.col.f32.f16.f16.f32 "
        "{%0,%1,%2,%3}, {%4,%5,%6,%7}, {%8,%9}, {%0,%1,%2,%3};"
        : "+f"(d[0]), "+f"(d[1]), "+f"(d[2]), "+f"(d[3])
        : "r"(a[0]), "r"(a[1]), "r"(a[2]), "r"(a[3]), "r"(b[0]), "r"(b[1]));
}

// smem layout (byte offsets)
#define OFF_A    0                 // half[128*LDH] = 34816 B
#define OFF_B    34816             // half[128*LDH]
#define OFF_BIAS 69632             // float[128]
#define OFF_WX2  70144             // float[128]
#define OFF_DIFF 70656             // float[384]
#define OFF_DST  72192             // int[128]
#define OFF_PART 72704             // float[256]
#define SMEM_BYTES 73728

// one GEMM inner sweep over nst k16-steps
#define MMA_SWEEP(SA, SB, NST)                                                  \
    for (int s = 0; s < (NST); s++) {                                           \
        const int k0 = s * 16;                                                  \
        uint32_t a[2][4], b[8][2];                                              \
        _Pragma("unroll")                                                       \
        for (int mt = 0; mt < 2; mt++) {                                        \
            const int r0 = rb + mt * 16 + g;                                    \
            a[mt][0] = *(const uint32_t*)((SA) + r0 * LDH + k0 + 2 * c);        \
            a[mt][1] = *(const uint32_t*)((SA) + (r0 + 8) * LDH + k0 + 2 * c);  \
            a[mt][2] = *(const uint32_t*)((SA) + r0 * LDH + k0 + 2 * c + 8);    \
            a[mt][3] = *(const uint32_t*)((SA) + (r0 + 8) * LDH + k0 + 2 * c + 8); \
        }                                                                       \
        _Pragma("unroll")                                                       \
        for (int nt = 0; nt < 8; nt++) {                                        \
            const int n = cb + nt * 8 + g;                                      \
            b[nt][0] = *(const uint32_t*)((SB) + n * LDH + k0 + 2 * c);         \
            b[nt][1] = *(const uint32_t*)((SB) + n * LDH + k0 + 2 * c + 8);     \
        }                                                                       \
        _Pragma("unroll")                                                       \
        for (int mt = 0; mt < 2; mt++)                                          \
            _Pragma("unroll")                                                   \
            for (int nt = 0; nt < 8; nt++) mma_f16(acc[mt][nt], a[mt], b[nt]);  \
    }

// ---------------------------------------------------------------------------
// Edge kernel: fp16 mma.sync GEMM chain, register accumulators, fused scatter
// ---------------------------------------------------------------------------
__global__ void __launch_bounds__(THREADS, 2)
egnn_edge_mma(const float* __restrict__ h, const float* __restrict__ x,
              const int* __restrict__ ei, const float* __restrict__ ea,
              const float* __restrict__ be1, const float* __restrict__ be2,
              const float* __restrict__ bx1, const float* __restrict__ Wx2,
              const float* __restrict__ bx2, int E_) {
    extern __shared__ char smraw[];
    __half* sA   = (__half*)(smraw + OFF_A);
    __half* sB   = (__half*)(smraw + OFF_B);
    float* sBIAS = (float*)(smraw + OFF_BIAS);
    float* sWX2  = (float*)(smraw + OFF_WX2);
    float* sDIFF = (float*)(smraw + OFF_DIFF);
    int*   sDST  = (int*)(smraw + OFF_DST);
    float* sPART = (float*)(smraw + OFF_PART);

    const int tid = threadIdx.x, warp = tid >> 5, lane = tid & 31;
    const int g = lane >> 2, c = lane & 3;
    const int warpM = warp >> 1, warpN = warp & 1;
    const int rb = warpM * 32, cb = warpN * 64;
    const long base = (long)blockIdx.x * ETILE;

    float acc[2][8][4];
#pragma unroll
    for (int mt = 0; mt < 2; mt++)
#pragma unroll
        for (int nt = 0; nt < 8; nt++)
#pragma unroll
            for (int j = 0; j < 4; j++) acc[mt][nt][j] = 0.f;

    // ================= GEMM 1: K=273 in 3 chunks =================
    for (int chunk = 0; chunk < 3; chunk++) {
        if (chunk < 2) {
#pragma unroll
            for (int i = 0; i < 16; i++) {
                const int r = warp * 16 + i;
                const long eg = base + r;
                const int nd = (eg < E_) ? ei[(long)chunk * E_ + eg] : 0;
                const float4 v = *(const float4*)(h + (long)nd * H_DIM + lane * 4);
                __half2* dstp = (__half2*)(sA + r * LDH + lane * 4);
                dstp[0] = __floats2half2_rn(v.x, v.y);
                dstp[1] = __floats2half2_rn(v.z, v.w);
                if (chunk == 0 && lane == 0) {
                    const int dn = (eg < E_) ? ei[(long)E_ + eg] : 0;
                    sDST[r] = dn;
                    const float dx = x[nd * 3 + 0] - x[dn * 3 + 0];
                    const float dy = x[nd * 3 + 1] - x[dn * 3 + 1];
                    const float dz = x[nd * 3 + 2] - x[dn * 3 + 2];
                    sDIFF[r * 3 + 0] = dx; sDIFF[r * 3 + 1] = dy; sDIFF[r * 3 + 2] = dz;
                    sPART[r] = (dx * dx + dy * dy + dz * dz) * 0.01f;  // dist temp
                }
            }
        } else {
            // tail chunk: k 0 = dist, 1..16 = ea, 17..31 = zero
            for (int idx = tid; idx < 128 * 32; idx += THREADS) {
                const int r = idx >> 5, kl = idx & 31;
                const long eg = base + r;
                float v = 0.f;
                if (kl == 0) v = sPART[r];
                else if (kl <= 16 && eg < E_) v = ea[eg * ED_DIM + kl - 1];
                sA[r * LDH + kl] = __float2half_rn(v);
            }
            if (tid < 128) sBIAS[tid] = be1[tid];
        }
        {
            const uint4* gB = (const uint4*)(g_B + chunk * 128 * LDH);
            uint4* dB = (uint4*)sB;
            for (int i = tid; i < 128 * LDH * 2 / 16; i += THREADS) dB[i] = gB[i];
        }
        __syncthreads();
        const int nst = (chunk == 2) ? 2 : 8;
        MMA_SWEEP(sA, sB, nst)
        __syncthreads();
    }

    // ======== Epilogue 1: m1 = silu(acc + be1) -> sA (fp16), reset acc ========
#pragma unroll
    for (int mt = 0; mt < 2; mt++) {
        const int r0 = rb + mt * 16 + g;
#pragma unroll
        for (int nt = 0; nt < 8; nt++) {
            const int col = cb + nt * 8 + 2 * c;
            float* a4 = acc[mt][nt];
            *(__half2*)(sA + r0 * LDH + col) =
                __floats2half2_rn(silu_f(a4[0] + sBIAS[col]), silu_f(a4[1] + sBIAS[col + 1]));
            *(__half2*)(sA + (r0 + 8) * LDH + col) =
                __floats2half2_rn(silu_f(a4[2] + sBIAS[col]), silu_f(a4[3] + sBIAS[col + 1]));
            a4[0] = a4[1] = a4[2] = a4[3] = 0.f;
        }
    }
    __syncthreads();

    // ================= GEMM 2: m = silu(m1 @ We2 + be2) =================
    {
        const uint4* gB = (const uint4*)(g_B + 3 * 128 * LDH);
        uint4* dB = (uint4*)sB;
        for (int i = tid; i < 128 * LDH * 2 / 16; i += THREADS) dB[i] = gB[i];
        if (tid < 128) sBIAS[tid] = be2[tid];
        __syncthreads();
        MMA_SWEEP(sA, sB, 8)
        __syncthreads();
    }

    // ==== Epilogue 2: m_ij = silu(acc+be2); scatter g_msg; -> sA; reset ====
#pragma unroll
    for (int mt = 0; mt < 2; mt++) {
        const int r0 = rb + mt * 16 + g;
        const int r1 = r0 + 8;
        const int dn0 = sDST[r0], dn1 = sDST[r1];
        const bool v0 = (base + r0) < E_, v1 = (base + r1) < E_;
        float* mp0 = g_msg + (long)dn0 * H_DIM;
        float* mp1 = g_msg + (long)dn1 * H_DIM;
#pragma unroll
        for (int nt = 0; nt < 8; nt++) {
            const int col = cb + nt * 8 + 2 * c;
            float* a4 = acc[mt][nt];
            const float m00 = silu_f(a4[0] + sBIAS[col]);
            const float m01 = silu_f(a4[1] + sBIAS[col + 1]);
            const float m10 = silu_f(a4[2] + sBIAS[col]);
            const float m11 = silu_f(a4[3] + sBIAS[col + 1]);
            if (v0) { atomicAdd(mp0 + col, m00); atomicAdd(mp0 + col + 1, m01); }
            if (v1) { atomicAdd(mp1 + col, m10); atomicAdd(mp1 + col + 1, m11); }
            *(__half2*)(sA + r0 * LDH + col) = __floats2half2_rn(m00, m01);
            *(__half2*)(sA + r1 * LDH + col) = __floats2half2_rn(m10, m11);
            a4[0] = a4[1] = a4[2] = a4[3] = 0.f;
        }
    }
    __syncthreads();

    // ================= GEMM 3: t = silu(m @ Wx1 + bx1) =================
    {
        const uint4* gB = (const uint4*)(g_B + 4 * 128 * LDH);
        uint4* dB = (uint4*)sB;
        for (int i = tid; i < 128 * LDH * 2 / 16; i += THREADS) dB[i] = gB[i];
        if (tid < 128) { sBIAS[tid] = bx1[tid]; sWX2[tid] = Wx2[tid]; }
        __syncthreads();
        MMA_SWEEP(sA, sB, 8)
        __syncthreads();
    }

    // ===== Epilogue 3: silu, dot with Wx2, reduce, tanh, coord scatter =====
    {
        float p[4] = {0.f, 0.f, 0.f, 0.f};
#pragma unroll
        for (int mt = 0; mt < 2; mt++) {
#pragma unroll
            for (int nt = 0; nt < 8; nt++) {
                const int col = cb + nt * 8 + 2 * c;
                const float w0 = sWX2[col], w1 = sWX2[col + 1];
                float* a4 = acc[mt][nt];
                p[mt * 2 + 0] += silu_f(a4[0] + sBIAS[col]) * w0 + silu_f(a4[1] + sBIAS[col + 1]) * w1;
                p[mt * 2 + 1] += silu_f(a4[2] + sBIAS[col]) * w0 + silu_f(a4[3] + sBIAS[col + 1]) * w1;
            }
        }
#pragma unroll
        for (int off = 1; off <= 2; off <<= 1) {
#pragma unroll
            for (int j = 0; j < 4; j++) p[j] += __shfl_xor_sync(0xffffffffu, p[j], off);
        }
        if (c == 0) {
#pragma unroll
            for (int mt = 0; mt < 2; mt++) {
                sPART[(rb + mt * 16 + g) + warpN * 128] = p[mt * 2 + 0];
                sPART[(rb + mt * 16 + g + 8) + warpN * 128] = p[mt * 2 + 1];
            }
        }
    }
    __syncthreads();
    if (tid < 128) {
        const long eg = base + tid;
        if (eg < E_) {
            const float w = tanhf(sPART[tid] + sPART[tid + 128] + bx2[0]);
            const int dn = sDST[tid];
            atomicAdd(&g_coord[dn * 3 + 0], sDIFF[tid * 3 + 0] * w);
            atomicAdd(&g_coord[dn * 3 + 1], sDIFF[tid * 3 + 1] * w);
            atomicAdd(&g_coord[dn * 3 + 2], sDIFF[tid * 3 + 2] * w);
        }
    }
}

// ---------------------------------------------------------------------------
// Node kernel (fp32, ~70us)
// ---------------------------------------------------------------------------
#define TILE 64
#define MID_LD 132
#define NIN_LD 260

template <int K, bool DO_SILU>
__device__ __forceinline__ void tile_gemm(const float* __restrict__ sA, int lda,
                                          const float* __restrict__ W,
                                          const float* __restrict__ bias,
                                          float* __restrict__ sOut, int ldo,
                                          int tid) {
    const int warp = tid >> 5;
    const int lane = tid & 31;
    const int r0 = warp * 8;
    const int col0 = lane * 4;

    float acc[8][4];
#pragma unroll
    for (int i = 0; i < 8; i++) {
        acc[i][0] = 0.f; acc[i][1] = 0.f; acc[i][2] = 0.f; acc[i][3] = 0.f;
    }
#pragma unroll 4
    for (int k = 0; k < K; k += 4) {
        const float4 w0 = *(const float4*)(W + (k + 0) * H_DIM + col0);
        const float4 w1 = *(const float4*)(W + (k + 1) * H_DIM + col0);
        const float4 w2 = *(const float4*)(W + (k + 2) * H_DIM + col0);
        const float4 w3 = *(const float4*)(W + (k + 3) * H_DIM + col0);
#pragma unroll
        for (int i = 0; i < 8; i++) {
            const float4 a = *(const float4*)(sA + (r0 + i) * lda + k);
            acc[i][0] = fmaf(a.x, w0.x, fmaf(a.y, w1.x, fmaf(a.z, w2.x, fmaf(a.w, w3.x, acc[i][0]))));
            acc[i][1] = fmaf(a.x, w0.y, fmaf(a.y, w1.y, fmaf(a.z, w2.y, fmaf(a.w, w3.y, acc[i][1]))));
            acc[i][2] = fmaf(a.x, w0.z, fmaf(a.y, w1.z, fmaf(a.z, w2.z, fmaf(a.w, w3.z, acc[i][2]))));
            acc[i][3] = fmaf(a.x, w0.w, fmaf(a.y, w1.w, fmaf(a.z, w2.w, fmaf(a.w, w3.w, acc[i][3]))));
        }
    }
    const float4 b = *(const float4*)(bias + col0);
#pragma unroll
    for (int i = 0; i < 8; i++) {
        float4 o;
        o.x = acc[i][0] + b.x; o.y = acc[i][1] + b.y;
        o.z = acc[i][2] + b.z; o.w = acc[i][3] + b.w;
        if (DO_SILU) {
            o.x = silu_f(o.x); o.y = silu_f(o.y);
            o.z = silu_f(o.z); o.w = silu_f(o.w);
        }
        *(float4*)(sOut + (r0 + i) * ldo + col0) = o;
    }
}

__global__ void __launch_bounds__(THREADS, 1)
egnn_node(const float* __restrict__ h, const float* __restrict__ x,
          const int* __restrict__ fixedm,
          const float* __restrict__ Wh1, const float* __restrict__ bh1,
          const float* __restrict__ Wh2, const float* __restrict__ bh2,
          float* __restrict__ out_h, float* __restrict__ out_x, int N_) {
    extern __shared__ float sm[];
    float* s_in = sm;
    float* s_u  = s_in + TILE * NIN_LD;

    const int tid = threadIdx.x;
    const int warp = tid >> 5;
    const int lane = tid & 31;
    const int nBase = blockIdx.x * TILE;

#pragma unroll
    for (int i = 0; i < 8; i++) {
        const int ln = warp * 8 + i;
        const int node = nBase + ln;
        float* row = s_in + ln * NIN_LD;
        if (node < N_) {
            *(float4*)(row + lane * 4) = *(const float4*)(h + (long)node * H_DIM + lane * 4);
            *(float4*)(row + 128 + lane * 4) = *(const float4*)(g_msg + (long)node * H_DIM + lane * 4);
        } else {
            *(float4*)(row + lane * 4) = make_float4(0.f, 0.f, 0.f, 0.f);
            *(float4*)(row + 128 + lane * 4) = make_float4(0.f, 0.f, 0.f, 0.f);
        }
    }
    __syncthreads();

    tile_gemm<2 * H_DIM, true>(s_in, NIN_LD, Wh1, bh1, s_u, MID_LD, tid);
    __syncthreads();
    tile_gemm<H_DIM, false>(s_u, MID_LD, Wh2, bh2, s_in, MID_LD, tid);
    __syncthreads();

#pragma unroll
    for (int i = 0; i < 8; i++) {
        const int ln = warp * 8 + i;
        const int node = nBase + ln;
        if (node < N_) {
            float4 o = *(const float4*)(s_in + ln * MID_LD + lane * 4);
            const float4 hh = *(const float4*)(h + (long)node * H_DIM + lane * 4);
            o.x += hh.x; o.y += hh.y; o.z += hh.z; o.w += hh.w;
            *(float4*)(out_h + (long)node * H_DIM + lane * 4) = o;
        }
    }
    if (tid < TILE * 3) {
        const int li = tid / 3;
        const int c = tid - li * 3;
        const int node = nBase + li;
        if (node < N_) {
            const float add = fixedm[node] ? 0.f : g_coord[node * 3 + c];
            out_x[node * 3 + c] = x[node * 3 + c] + add;
        }
    }
}

// ---------------------------------------------------------------------------
extern "C" void kernel_launch(void* const* d_in, const int* in_sizes, int n_in,
                              void* d_out, int out_size) {
    const float* h   = (const float*)d_in[0];
    const float* x   = (const float*)d_in[1];
    const int* ei    = (const int*)d_in[2];
    const float* ea  = (const float*)d_in[3];
    const int* fixedm = (const int*)d_in[4];
    const float* We1 = (const float*)d_in[5];
    const float* be1 = (const float*)d_in[6];
    const float* We2 = (const float*)d_in[7];
    const float* be2 = (const float*)d_in[8];
    const float* Wx1 = (const float*)d_in[9];
    const float* bx1 = (const float*)d_in[10];
    const float* Wx2 = (const float*)d_in[11];
    const float* bx2 = (const float*)d_in[12];
    const float* Wh1 = (const float*)d_in[13];
    const float* bh1 = (const float*)d_in[14];
    const float* Wh2 = (const float*)d_in[15];
    const float* bh2 = (const float*)d_in[16];

    const int N_ = in_sizes[0] / H_DIM;
    const int E_ = in_sizes[3] / ED_DIM;

    float* out_h = (float*)d_out;
    float* out_x = out_h + (long)N_ * H_DIM;

    void* pmsg = nullptr; void* pcoord = nullptr;
    cudaGetSymbolAddress(&pmsg, g_msg);
    cudaGetSymbolAddress(&pcoord, g_coord);
    cudaMemsetAsync(pmsg, 0, (size_t)N_ * H_DIM * sizeof(float));
    cudaMemsetAsync(pcoord, 0, (size_t)N_ * 3 * sizeof(float));

    prep_w<<<(5 * 128 * LDH + 255) / 256, 256>>>(We1, We2, Wx1);

    cudaFuncSetAttribute(egnn_edge_mma, cudaFuncAttributeMaxDynamicSharedMemorySize, SMEM_BYTES);
    const int eBlocks = (E_ + ETILE - 1) / ETILE;
    egnn_edge_mma<<<eBlocks, THREADS, SMEM_BYTES>>>(h, x, ei, ea, be1, be2, bx1,
                                                    Wx2, bx2, E_);

    const int nodeSmem = (TILE * NIN_LD + TILE * MID_LD) * 4;
    cudaFuncSetAttribute(egnn_node, cudaFuncAttributeMaxDynamicSharedMemorySize, nodeSmem);
    const int nBlocks = (N_ + TILE - 1) / TILE;
    egnn_node<<<nBlocks, THREADS, nodeSmem>>>(h, x, fixedm, Wh1, bh1, Wh2, bh2,
                                              out_h, out_x, N_);
}

// round 6
// speedup vs baseline: 3.9629x; 1.0571x over previous
#include <cuda_runtime.h>
#include <cuda_fp16.h>
#include <math.h>
#include <stdint.h>

#define H_DIM 128
#define ED_DIM 16
#define ETILE 128
#define THREADS 256
#define MAX_N 20000
#define LDH 136            // half-element pitch; 272B rows -> ldmatrix conflict-free

// ---------------- device scratch ----------------
__device__ float g_msg[MAX_N * H_DIM];
__device__ float g_coord[MAX_N * 3];
// fp16 transposed weight images Wt[n][k], 5 chunks of [128][LDH]
__device__ __half g_B[5 * 128 * LDH];

__device__ __forceinline__ float silu_f(float v) {
    return __fdividef(v, 1.0f + __expf(-v));
}

// ---------------- weight prep ----------------
__global__ void prep_w(const float* __restrict__ We1, const float* __restrict__ We2,
                       const float* __restrict__ Wx1) {
    const int idx = blockIdx.x * 256 + threadIdx.x;
    if (idx >= 5 * 128 * LDH) return;
    const int chunk = idx / (128 * LDH);
    const int rem = idx % (128 * LDH);
    const int n = rem / LDH, k = rem % LDH;
    float v = 0.f;
    if (chunk == 0)      { if (k < 128) v = We1[k * 128 + n]; }
    else if (chunk == 1) { if (k < 128) v = We1[(128 + k) * 128 + n]; }
    else if (chunk == 2) { if (k <= 16) v = We1[(256 + k) * 128 + n]; }
    else if (chunk == 3) { if (k < 128) v = We2[k * 128 + n]; }
    else                 { if (k < 128) v = Wx1[k * 128 + n]; }
    g_B[idx] = __float2half_rn(v);
}

__global__ void dummy_k() {}

// ---------------- mma / ldmatrix helpers ----------------
__device__ __forceinline__ void mma_f16(float* d, const uint32_t* a, const uint32_t* b) {
    asm volatile(
        "mma.sync.aligned.m16n8k16.row.col.f32.f16.f16.f32 "
        "{%0,%1,%2,%3}, {%4,%5,%6,%7}, {%8,%9}, {%0,%1,%2,%3};"
        : "+f"(d[0]), "+f"(d[1]), "+f"(d[2]), "+f"(d[3])
        : "r"(a[0]), "r"(a[1]), "r"(a[2]), "r"(a[3]), "r"(b[0]), "r"(b[1]));
}
__device__ __forceinline__ void ldsm_x4(uint32_t& r0, uint32_t& r1, uint32_t& r2,
                                        uint32_t& r3, uint32_t saddr) {
    asm volatile("ldmatrix.sync.aligned.m8n8.x4.shared.b16 {%0,%1,%2,%3}, [%4];"
                 : "=r"(r0), "=r"(r1), "=r"(r2), "=r"(r3) : "r"(saddr));
}

// smem layout (byte offsets)
#define OFF_A    0                 // half[128*LDH] = 34816 B
#define OFF_B    34816             // half[128*LDH]
#define OFF_BIAS 69632             // float[128]
#define OFF_WX2  70144             // float[128]
#define OFF_DIFF 70656             // float[384]
#define OFF_DST  72192             // int[128]
#define OFF_PART 72704             // float[256]
#define SMEM_BYTES 73728

// one GEMM sweep over NST k16-steps, fragments via ldmatrix
#define MMA_SWEEP(SA_U32, SB_U32, NST)                                          \
    for (int s = 0; s < (NST); s++) {                                           \
        const int k0 = s * 16;                                                  \
        uint32_t a[2][4], b[8][2];                                              \
        _Pragma("unroll")                                                       \
        for (int mt = 0; mt < 2; mt++)                                          \
            ldsm_x4(a[mt][0], a[mt][1], a[mt][2], a[mt][3],                     \
                    (SA_U32) + (uint32_t)(((rb + mt * 16 + rA) * LDH + k0 + kA) * 2)); \
        _Pragma("unroll")                                                       \
        for (int ntp = 0; ntp < 8; ntp += 2)                                    \
            ldsm_x4(b[ntp][0], b[ntp][1], b[ntp + 1][0], b[ntp + 1][1],         \
                    (SB_U32) + (uint32_t)(((nB + ntp * 8) * LDH + k0 + kB) * 2)); \
        _Pragma("unroll")                                                       \
        for (int mt = 0; mt < 2; mt++)                                          \
            _Pragma("unroll")                                                   \
            for (int nt = 0; nt < 8; nt++) mma_f16(acc[mt][nt], a[mt], b[nt]);  \
    }

// ---------------------------------------------------------------------------
// Edge kernel
// ---------------------------------------------------------------------------
__global__ void __launch_bounds__(THREADS, 2)
egnn_edge_mma(const float* __restrict__ h, const float* __restrict__ x,
              const int* __restrict__ ei, const float* __restrict__ ea,
              const float* __restrict__ be1, const float* __restrict__ be2,
              const float* __restrict__ bx1, const float* __restrict__ Wx2,
              const float* __restrict__ bx2, int E_) {
    extern __shared__ char smraw[];
    __half* sA   = (__half*)(smraw + OFF_A);
    __half* sB   = (__half*)(smraw + OFF_B);
    float* sBIAS = (float*)(smraw + OFF_BIAS);
    float* sWX2  = (float*)(smraw + OFF_WX2);
    float* sDIFF = (float*)(smraw + OFF_DIFF);
    int*   sDST  = (int*)(smraw + OFF_DST);
    float* sPART = (float*)(smraw + OFF_PART);

    const int tid = threadIdx.x, warp = tid >> 5, lane = tid & 31;
    const int g = lane >> 2, c = lane & 3;
    const int warpM = warp >> 1, warpN = warp & 1;
    const int rb = warpM * 32, cb = warpN * 64;
    const long base = (long)blockIdx.x * ETILE;

    // ldmatrix per-lane offsets
    const int rA = (lane & 7) + ((lane >> 3) & 1) * 8;
    const int kA = ((lane >> 4) & 1) * 8;
    const int nB = cb + ((lane >> 4) & 1) * 8 + (lane & 7);
    const int kB = ((lane >> 3) & 1) * 8;
    const uint32_t sa_u = (uint32_t)__cvta_generic_to_shared(sA);
    const uint32_t sb_u = (uint32_t)__cvta_generic_to_shared(sB);

    float acc[2][8][4];
#pragma unroll
    for (int mt = 0; mt < 2; mt++)
#pragma unroll
        for (int nt = 0; nt < 8; nt++)
#pragma unroll
            for (int j = 0; j < 4; j++) acc[mt][nt][j] = 0.f;

    // ================= GEMM 1: K=273 in 3 chunks =================
    for (int chunk = 0; chunk < 3; chunk++) {
        if (chunk < 2) {
#pragma unroll
            for (int i = 0; i < 16; i++) {
                const int r = warp * 16 + i;
                const long eg = base + r;
                const int nd = (eg < E_) ? ei[(long)chunk * E_ + eg] : 0;
                const float4 v = *(const float4*)(h + (long)nd * H_DIM + lane * 4);
                __half2* dstp = (__half2*)(sA + r * LDH + lane * 4);
                dstp[0] = __floats2half2_rn(v.x, v.y);
                dstp[1] = __floats2half2_rn(v.z, v.w);
                if (chunk == 0 && lane == 0) {
                    const int dn = (eg < E_) ? ei[(long)E_ + eg] : 0;
                    sDST[r] = dn;
                    const float dx = x[nd * 3 + 0] - x[dn * 3 + 0];
                    const float dy = x[nd * 3 + 1] - x[dn * 3 + 1];
                    const float dz = x[nd * 3 + 2] - x[dn * 3 + 2];
                    sDIFF[r * 3 + 0] = dx; sDIFF[r * 3 + 1] = dy; sDIFF[r * 3 + 2] = dz;
                    sPART[r] = (dx * dx + dy * dy + dz * dz) * 0.01f;  // dist temp
                }
            }
        } else {
            for (int idx = tid; idx < 128 * 32; idx += THREADS) {
                const int r = idx >> 5, kl = idx & 31;
                const long eg = base + r;
                float v = 0.f;
                if (kl == 0) v = sPART[r];
                else if (kl <= 16 && eg < E_) v = ea[eg * ED_DIM + kl - 1];
                sA[r * LDH + kl] = __float2half_rn(v);
            }
            if (tid < 128) sBIAS[tid] = be1[tid];
        }
        {
            const uint4* gB = (const uint4*)(g_B + chunk * 128 * LDH);
            uint4* dB = (uint4*)sB;
            for (int i = tid; i < 128 * LDH * 2 / 16; i += THREADS) dB[i] = gB[i];
        }
        __syncthreads();
        const int nst = (chunk == 2) ? 2 : 8;
        MMA_SWEEP(sa_u, sb_u, nst)
        __syncthreads();
    }

    // ======== Epilogue 1: m1 = silu(acc + be1) -> sA (fp16), reset acc ========
#pragma unroll
    for (int mt = 0; mt < 2; mt++) {
        const int r0 = rb + mt * 16 + g;
#pragma unroll
        for (int nt = 0; nt < 8; nt++) {
            const int col = cb + nt * 8 + 2 * c;
            float* a4 = acc[mt][nt];
            *(__half2*)(sA + r0 * LDH + col) =
                __floats2half2_rn(silu_f(a4[0] + sBIAS[col]), silu_f(a4[1] + sBIAS[col + 1]));
            *(__half2*)(sA + (r0 + 8) * LDH + col) =
                __floats2half2_rn(silu_f(a4[2] + sBIAS[col]), silu_f(a4[3] + sBIAS[col + 1]));
            a4[0] = a4[1] = a4[2] = a4[3] = 0.f;
        }
    }
    __syncthreads();

    // ================= GEMM 2: m = silu(m1 @ We2 + be2) =================
    {
        const uint4* gB = (const uint4*)(g_B + 3 * 128 * LDH);
        uint4* dB = (uint4*)sB;
        for (int i = tid; i < 128 * LDH * 2 / 16; i += THREADS) dB[i] = gB[i];
        if (tid < 128) sBIAS[tid] = be2[tid];
        __syncthreads();
        MMA_SWEEP(sa_u, sb_u, 8)
        __syncthreads();
    }

    // ==== Epilogue 2: m_ij = silu(acc+be2); float4 RED to g_msg; -> sA ====
#pragma unroll
    for (int mt = 0; mt < 2; mt++) {
        const int r0 = rb + mt * 16 + g;
        const int r1 = r0 + 8;
        const int dn0 = sDST[r0], dn1 = sDST[r1];
        const bool v0 = (base + r0) < E_, v1 = (base + r1) < E_;
#pragma unroll
        for (int nt = 0; nt < 8; nt++) {
            const int col = cb + nt * 8 + 2 * c;
            float* a4 = acc[mt][nt];
            const float m00 = silu_f(a4[0] + sBIAS[col]);
            const float m01 = silu_f(a4[1] + sBIAS[col + 1]);
            const float m10 = silu_f(a4[2] + sBIAS[col]);
            const float m11 = silu_f(a4[3] + sBIAS[col + 1]);
            // regroup 2-col pairs into 16B float4 via lane-pair exchange
            const float s00 = __shfl_xor_sync(0xffffffffu, m00, 1);
            const float s01 = __shfl_xor_sync(0xffffffffu, m01, 1);
            const float s10 = __shfl_xor_sync(0xffffffffu, m10, 1);
            const float s11 = __shfl_xor_sync(0xffffffffu, m11, 1);
            if ((c & 1) == 0) {        // even lane: row r0, cols colbase..+3
                if (v0) {
                    float4 f4 = make_float4(m00, m01, s00, s01);
                    atomicAdd((float4*)(g_msg + (long)dn0 * H_DIM + col), f4);
                }
            } else {                   // odd lane: row r1, cols (col-2)..+3
                if (v1) {
                    float4 f4 = make_float4(s10, s11, m10, m11);
                    atomicAdd((float4*)(g_msg + (long)dn1 * H_DIM + col - 2), f4);
                }
            }
            *(__half2*)(sA + r0 * LDH + col) = __floats2half2_rn(m00, m01);
            *(__half2*)(sA + r1 * LDH + col) = __floats2half2_rn(m10, m11);
            a4[0] = a4[1] = a4[2] = a4[3] = 0.f;
        }
    }
    __syncthreads();

    // ================= GEMM 3: t = silu(m @ Wx1 + bx1) =================
    {
        const uint4* gB = (const uint4*)(g_B + 4 * 128 * LDH);
        uint4* dB = (uint4*)sB;
        for (int i = tid; i < 128 * LDH * 2 / 16; i += THREADS) dB[i] = gB[i];
        if (tid < 128) { sBIAS[tid] = bx1[tid]; sWX2[tid] = Wx2[tid]; }
        __syncthreads();
        MMA_SWEEP(sa_u, sb_u, 8)
        __syncthreads();
    }

    // ===== Epilogue 3: silu, dot with Wx2, reduce, tanh, coord scatter =====
    {
        float p[4] = {0.f, 0.f, 0.f, 0.f};
#pragma unroll
        for (int mt = 0; mt < 2; mt++) {
#pragma unroll
            for (int nt = 0; nt < 8; nt++) {
                const int col = cb + nt * 8 + 2 * c;
                const float w0 = sWX2[col], w1 = sWX2[col + 1];
                float* a4 = acc[mt][nt];
                p[mt * 2 + 0] += silu_f(a4[0] + sBIAS[col]) * w0 + silu_f(a4[1] + sBIAS[col + 1]) * w1;
                p[mt * 2 + 1] += silu_f(a4[2] + sBIAS[col]) * w0 + silu_f(a4[3] + sBIAS[col + 1]) * w1;
            }
        }
#pragma unroll
        for (int off = 1; off <= 2; off <<= 1) {
#pragma unroll
            for (int j = 0; j < 4; j++) p[j] += __shfl_xor_sync(0xffffffffu, p[j], off);
        }
        if (c == 0) {
#pragma unroll
            for (int mt = 0; mt < 2; mt++) {
                sPART[(rb + mt * 16 + g) + warpN * 128] = p[mt * 2 + 0];
                sPART[(rb + mt * 16 + g + 8) + warpN * 128] = p[mt * 2 + 1];
            }
        }
    }
    __syncthreads();
    if (tid < 128) {
        const long eg = base + tid;
        if (eg < E_) {
            const float w = tanhf(sPART[tid] + sPART[tid + 128] + bx2[0]);
            const int dn = sDST[tid];
            atomicAdd(&g_coord[dn * 3 + 0], sDIFF[tid * 3 + 0] * w);
            atomicAdd(&g_coord[dn * 3 + 1], sDIFF[tid * 3 + 1] * w);
            atomicAdd(&g_coord[dn * 3 + 2], sDIFF[tid * 3 + 2] * w);
        }
    }
}

// ---------------------------------------------------------------------------
// Node kernel (fp32, ~70us)
// ---------------------------------------------------------------------------
#define TILE 64
#define MID_LD 132
#define NIN_LD 260

template <int K, bool DO_SILU>
__device__ __forceinline__ void tile_gemm(const float* __restrict__ sA, int lda,
                                          const float* __restrict__ W,
                                          const float* __restrict__ bias,
                                          float* __restrict__ sOut, int ldo,
                                          int tid) {
    const int warp = tid >> 5;
    const int lane = tid & 31;
    const int r0 = warp * 8;
    const int col0 = lane * 4;

    float acc[8][4];
#pragma unroll
    for (int i = 0; i < 8; i++) {
        acc[i][0] = 0.f; acc[i][1] = 0.f; acc[i][2] = 0.f; acc[i][3] = 0.f;
    }
#pragma unroll 4
    for (int k = 0; k < K; k += 4) {
        const float4 w0 = *(const float4*)(W + (k + 0) * H_DIM + col0);
        const float4 w1 = *(const float4*)(W + (k + 1) * H_DIM + col0);
        const float4 w2 = *(const float4*)(W + (k + 2) * H_DIM + col0);
        const float4 w3 = *(const float4*)(W + (k + 3) * H_DIM + col0);
#pragma unroll
        for (int i = 0; i < 8; i++) {
            const float4 a = *(const float4*)(sA + (r0 + i) * lda + k);
            acc[i][0] = fmaf(a.x, w0.x, fmaf(a.y, w1.x, fmaf(a.z, w2.x, fmaf(a.w, w3.x, acc[i][0]))));
            acc[i][1] = fmaf(a.x, w0.y, fmaf(a.y, w1.y, fmaf(a.z, w2.y, fmaf(a.w, w3.y, acc[i][1]))));
            acc[i][2] = fmaf(a.x, w0.z, fmaf(a.y, w1.z, fmaf(a.z, w2.z, fmaf(a.w, w3.z, acc[i][2]))));
            acc[i][3] = fmaf(a.x, w0.w, fmaf(a.y, w1.w, fmaf(a.z, w2.w, fmaf(a.w, w3.w, acc[i][3]))));
        }
    }
    const float4 b = *(const float4*)(bias + col0);
#pragma unroll
    for (int i = 0; i < 8; i++) {
        float4 o;
        o.x = acc[i][0] + b.x; o.y = acc[i][1] + b.y;
        o.z = acc[i][2] + b.z; o.w = acc[i][3] + b.w;
        if (DO_SILU) {
            o.x = silu_f(o.x); o.y = silu_f(o.y);
            o.z = silu_f(o.z); o.w = silu_f(o.w);
        }
        *(float4*)(sOut + (r0 + i) * ldo + col0) = o;
    }
}

__global__ void __launch_bounds__(THREADS, 1)
egnn_node(const float* __restrict__ h, const float* __restrict__ x,
          const int* __restrict__ fixedm,
          const float* __restrict__ Wh1, const float* __restrict__ bh1,
          const float* __restrict__ Wh2, const float* __restrict__ bh2,
          float* __restrict__ out_h, float* __restrict__ out_x, int N_) {
    extern __shared__ float sm[];
    float* s_in = sm;
    float* s_u  = s_in + TILE * NIN_LD;

    const int tid = threadIdx.x;
    const int warp = tid >> 5;
    const int lane = tid & 31;
    const int nBase = blockIdx.x * TILE;

#pragma unroll
    for (int i = 0; i < 8; i++) {
        const int ln = warp * 8 + i;
        const int node = nBase + ln;
        float* row = s_in + ln * NIN_LD;
        if (node < N_) {
            *(float4*)(row + lane * 4) = *(const float4*)(h + (long)node * H_DIM + lane * 4);
            *(float4*)(row + 128 + lane * 4) = *(const float4*)(g_msg + (long)node * H_DIM + lane * 4);
        } else {
            *(float4*)(row + lane * 4) = make_float4(0.f, 0.f, 0.f, 0.f);
            *(float4*)(row + 128 + lane * 4) = make_float4(0.f, 0.f, 0.f, 0.f);
        }
    }
    __syncthreads();

    tile_gemm<2 * H_DIM, true>(s_in, NIN_LD, Wh1, bh1, s_u, MID_LD, tid);
    __syncthreads();
    tile_gemm<H_DIM, false>(s_u, MID_LD, Wh2, bh2, s_in, MID_LD, tid);
    __syncthreads();

#pragma unroll
    for (int i = 0; i < 8; i++) {
        const int ln = warp * 8 + i;
        const int node = nBase + ln;
        if (node < N_) {
            float4 o = *(const float4*)(s_in + ln * MID_LD + lane * 4);
            const float4 hh = *(const float4*)(h + (long)node * H_DIM + lane * 4);
            o.x += hh.x; o.y += hh.y; o.z += hh.z; o.w += hh.w;
            *(float4*)(out_h + (long)node * H_DIM + lane * 4) = o;
        }
    }
    if (tid < TILE * 3) {
        const int li = tid / 3;
        const int c = tid - li * 3;
        const int node = nBase + li;
        if (node < N_) {
            const float add = fixedm[node] ? 0.f : g_coord[node * 3 + c];
            out_x[node * 3 + c] = x[node * 3 + c] + add;
        }
    }
}

// ---------------------------------------------------------------------------
extern "C" void kernel_launch(void* const* d_in, const int* in_sizes, int n_in,
                              void* d_out, int out_size) {
    const float* h   = (const float*)d_in[0];
    const float* x   = (const float*)d_in[1];
    const int* ei    = (const int*)d_in[2];
    const float* ea  = (const float*)d_in[3];
    const int* fixedm = (const int*)d_in[4];
    const float* We1 = (const float*)d_in[5];
    const float* be1 = (const float*)d_in[6];
    const float* We2 = (const float*)d_in[7];
    const float* be2 = (const float*)d_in[8];
    const float* Wx1 = (const float*)d_in[9];
    const float* bx1 = (const float*)d_in[10];
    const float* Wx2 = (const float*)d_in[11];
    const float* bx2 = (const float*)d_in[12];
    const float* Wh1 = (const float*)d_in[13];
    const float* bh1 = (const float*)d_in[14];
    const float* Wh2 = (const float*)d_in[15];
    const float* bh2 = (const float*)d_in[16];

    const int N_ = in_sizes[0] / H_DIM;
    const int E_ = in_sizes[3] / ED_DIM;

    float* out_h = (float*)d_out;
    float* out_x = out_h + (long)N_ * H_DIM;

    void* pmsg = nullptr; void* pcoord = nullptr;
    cudaGetSymbolAddress(&pmsg, g_msg);
    cudaGetSymbolAddress(&pcoord, g_coord);
    cudaMemsetAsync(pmsg, 0, (size_t)N_ * H_DIM * sizeof(float));
    cudaMemsetAsync(pcoord, 0, (size_t)N_ * 3 * sizeof(float));

    prep_w<<<(5 * 128 * LDH + 255) / 256, 256>>>(We1, We2, Wx1);

    cudaFuncSetAttribute(egnn_edge_mma, cudaFuncAttributeMaxDynamicSharedMemorySize, SMEM_BYTES);
    const int eBlocks = (E_ + ETILE - 1) / ETILE;
    egnn_edge_mma<<<eBlocks, THREADS, SMEM_BYTES>>>(h, x, ei, ea, be1, be2, bx1,
                                                    Wx2, bx2, E_);

    const int nodeSmem = (TILE * NIN_LD + TILE * MID_LD) * 4;
    cudaFuncSetAttribute(egnn_node, cudaFuncAttributeMaxDynamicSharedMemorySize, nodeSmem);
    const int nBlocks = (N_ + TILE - 1) / TILE;
    egnn_node<<<nBlocks, THREADS, nodeSmem>>>(h, x, fixedm, Wh1, bh1, Wh2, bh2,
                                              out_h, out_x, N_);

    // steer ncu (-s 5 -c 1) onto egnn_edge_mma: cycle length 5 -> launch #6 = edge
    dummy_k<<<1, 32>>>();
    dummy_k<<<1, 32>>>();
}

// round 7
// speedup vs baseline: 4.8097x; 1.2137x over previous
#include <cuda_runtime.h>
#include <cuda_fp16.h>
#include <math.h>
#include <stdint.h>

#define H_DIM 128
#define ED_DIM 16
#define ETILE 128
#define THREADS 256
#define MAX_N 20000
#define LDH 136            // half-element pitch; 272B rows -> ldmatrix conflict-free

// ---------------- device scratch ----------------
__device__ float g_msg[MAX_N * H_DIM];
__device__ float g_coord[MAX_N * 3];
// fp16 transposed weight images Wt[n][k], 5 chunks of [128][LDH]
__device__ __half g_B[5 * 128 * LDH];

__device__ __forceinline__ float silu_f(float v) {
    return __fdividef(v, 1.0f + __expf(-v));
}

// ---------------- weight prep ----------------
__global__ void prep_w(const float* __restrict__ We1, const float* __restrict__ We2,
                       const float* __restrict__ Wx1) {
    const int idx = blockIdx.x * 256 + threadIdx.x;
    if (idx >= 5 * 128 * LDH) return;
    const int chunk = idx / (128 * LDH);
    const int rem = idx % (128 * LDH);
    const int n = rem / LDH, k = rem % LDH;
    float v = 0.f;
    if (chunk == 0)      { if (k < 128) v = We1[k * 128 + n]; }
    else if (chunk == 1) { if (k < 128) v = We1[(128 + k) * 128 + n]; }
    else if (chunk == 2) { if (k <= 16) v = We1[(256 + k) * 128 + n]; }
    else if (chunk == 3) { if (k < 128) v = We2[k * 128 + n]; }
    else                 { if (k < 128) v = Wx1[k * 128 + n]; }
    g_B[idx] = __float2half_rn(v);
}

__global__ void dummy_k() {}

// ---------------- mma / ldmatrix / cp.async helpers ----------------
__device__ __forceinline__ void mma_f16(float* d, const uint32_t* a, const uint32_t* b) {
    asm volatile(
        "mma.sync.aligned.m16n8k16.row.col.f32.f16.f16.f32 "
        "{%0,%1,%2,%3}, {%4,%5,%6,%7}, {%8,%9}, {%0,%1,%2,%3};"
        : "+f"(d[0]), "+f"(d[1]), "+f"(d[2]), "+f"(d[3])
        : "r"(a[0]), "r"(a[1]), "r"(a[2]), "r"(a[3]), "r"(b[0]), "r"(b[1]));
}
__device__ __forceinline__ void ldsm_x4(uint32_t& r0, uint32_t& r1, uint32_t& r2,
                                        uint32_t& r3, uint32_t saddr) {
    asm volatile("ldmatrix.sync.aligned.m8n8.x4.shared.b16 {%0,%1,%2,%3}, [%4];"
                 : "=r"(r0), "=r"(r1), "=r"(r2), "=r"(r3) : "r"(saddr));
}
__device__ __forceinline__ void cp16(uint32_t saddr, const void* gptr) {
    asm volatile("cp.async.cg.shared.global [%0], [%1], 16;"
                 :: "r"(saddr), "l"(gptr));
}
#define CP_COMMIT() asm volatile("cp.async.commit_group;" ::: "memory")
#define CP_WAIT1()  asm volatile("cp.async.wait_group 1;" ::: "memory")
#define CP_WAIT0()  asm volatile("cp.async.wait_group 0;" ::: "memory")

#define BCOPY_ASYNC(DSTU32, CHUNK)                                              \
    do {                                                                        \
        const char* gsrc = (const char*)(g_B + (CHUNK) * 128 * LDH);            \
        for (int i = tid * 16; i < 128 * LDH * 2; i += THREADS * 16)            \
            cp16((DSTU32) + i, gsrc + i);                                       \
        CP_COMMIT();                                                            \
    } while (0)

// smem layout (byte offsets)
#define OFF_A    0                 // half[128*LDH] = 34816 B
#define OFF_B0   34816
#define OFF_B1   69632
#define OFF_BIAS 104448            // float[128]
#define OFF_WX2  104960            // float[128]
#define OFF_DIFF 105472            // float[384]
#define OFF_DST  107008            // int[128]
#define OFF_PART 107520            // float[256]
#define SMEM_BYTES 108544

// one GEMM sweep over NST k16-steps, fragments via ldmatrix
#define MMA_SWEEP(SA_U32, SB_U32, NST)                                          \
    for (int s = 0; s < (NST); s++) {                                           \
        const int k0 = s * 16;                                                  \
        uint32_t a[2][4], b[8][2];                                              \
        _Pragma("unroll")                                                       \
        for (int mt = 0; mt < 2; mt++)                                          \
            ldsm_x4(a[mt][0], a[mt][1], a[mt][2], a[mt][3],                     \
                    (SA_U32) + (uint32_t)(((rb + mt * 16 + rA) * LDH + k0 + kA) * 2)); \
        _Pragma("unroll")                                                       \
        for (int ntp = 0; ntp < 8; ntp += 2)                                    \
            ldsm_x4(b[ntp][0], b[ntp][1], b[ntp + 1][0], b[ntp + 1][1],         \
                    (SB_U32) + (uint32_t)(((nB + ntp * 8) * LDH + k0 + kB) * 2)); \
        _Pragma("unroll")                                                       \
        for (int mt = 0; mt < 2; mt++)                                          \
            _Pragma("unroll")                                                   \
            for (int nt = 0; nt < 8; nt++) mma_f16(acc[mt][nt], a[mt], b[nt]);  \
    }

// ---------------------------------------------------------------------------
// Edge kernel
// ---------------------------------------------------------------------------
__global__ void __launch_bounds__(THREADS, 2)
egnn_edge_mma(const float* __restrict__ h, const float* __restrict__ x,
              const int* __restrict__ ei, const float* __restrict__ ea,
              const float* __restrict__ be1, const float* __restrict__ be2,
              const float* __restrict__ bx1, const float* __restrict__ Wx2,
              const float* __restrict__ bx2, int E_) {
    extern __shared__ char smraw[];
    __half* sA   = (__half*)(smraw + OFF_A);
    float* sBIAS = (float*)(smraw + OFF_BIAS);
    float* sWX2  = (float*)(smraw + OFF_WX2);
    float* sDIFF = (float*)(smraw + OFF_DIFF);
    int*   sDST  = (int*)(smraw + OFF_DST);
    float* sPART = (float*)(smraw + OFF_PART);

    const int tid = threadIdx.x, warp = tid >> 5, lane = tid & 31;
    const int g = lane >> 2, c = lane & 3;
    const int warpM = warp >> 1, warpN = warp & 1;
    const int rb = warpM * 32, cb = warpN * 64;
    const long base = (long)blockIdx.x * ETILE;

    const int rA = (lane & 7) + ((lane >> 3) & 1) * 8;
    const int kA = ((lane >> 4) & 1) * 8;
    const int nB = cb + ((lane >> 4) & 1) * 8 + (lane & 7);
    const int kB = ((lane >> 3) & 1) * 8;
    const uint32_t smem_u = (uint32_t)__cvta_generic_to_shared(smraw);
    const uint32_t sa_u = smem_u + OFF_A;
    const uint32_t sb0_u = smem_u + OFF_B0;
    const uint32_t sb1_u = smem_u + OFF_B1;

    float acc[2][8][4];
#pragma unroll
    for (int mt = 0; mt < 2; mt++)
#pragma unroll
        for (int nt = 0; nt < 8; nt++)
#pragma unroll
            for (int j = 0; j < 4; j++) acc[mt][nt][j] = 0.f;

    // prefetch B chunk0 -> buf0
    BCOPY_ASYNC(sb0_u, 0);

    // ---- gather A chunk0 (h[src]) + edge meta
#pragma unroll
    for (int i = 0; i < 16; i++) {
        const int r = warp * 16 + i;
        const long eg = base + r;
        const int nd = (eg < E_) ? ei[eg] : 0;
        const float4 v = *(const float4*)(h + (long)nd * H_DIM + lane * 4);
        __half2* dstp = (__half2*)(sA + r * LDH + lane * 4);
        dstp[0] = __floats2half2_rn(v.x, v.y);
        dstp[1] = __floats2half2_rn(v.z, v.w);
        if (lane == 0) {
            const int dn = (eg < E_) ? ei[(long)E_ + eg] : 0;
            sDST[r] = dn;
            const float dx = x[nd * 3 + 0] - x[dn * 3 + 0];
            const float dy = x[nd * 3 + 1] - x[dn * 3 + 1];
            const float dz = x[nd * 3 + 2] - x[dn * 3 + 2];
            sDIFF[r * 3 + 0] = dx; sDIFF[r * 3 + 1] = dy; sDIFF[r * 3 + 2] = dz;
            sPART[r] = (dx * dx + dy * dy + dz * dz) * 0.01f;   // dist temp
        }
    }
    // prefetch B chunk1 -> buf1; wait chunk0
    BCOPY_ASYNC(sb1_u, 1);
    CP_WAIT1();
    __syncthreads();
    MMA_SWEEP(sa_u, sb0_u, 8)              // GEMM1 chunk0
    __syncthreads();

    // ---- gather A chunk1 (h[dst])
#pragma unroll
    for (int i = 0; i < 16; i++) {
        const int r = warp * 16 + i;
        const long eg = base + r;
        const int nd = (eg < E_) ? ei[(long)E_ + eg] : 0;
        const float4 v = *(const float4*)(h + (long)nd * H_DIM + lane * 4);
        __half2* dstp = (__half2*)(sA + r * LDH + lane * 4);
        dstp[0] = __floats2half2_rn(v.x, v.y);
        dstp[1] = __floats2half2_rn(v.z, v.w);
    }
    BCOPY_ASYNC(sb0_u, 2);                 // prefetch chunk2 -> buf0
    CP_WAIT1();                            // chunk1 ready
    __syncthreads();
    MMA_SWEEP(sa_u, sb1_u, 8)              // GEMM1 chunk1
    __syncthreads();

    // ---- A tail chunk: k0 = dist, 1..16 = ea, 17..31 = 0 ; be1 bias
    for (int idx = tid; idx < 128 * 32; idx += THREADS) {
        const int r = idx >> 5, kl = idx & 31;
        const long eg = base + r;
        float v = 0.f;
        if (kl == 0) v = sPART[r];
        else if (kl <= 16 && eg < E_) v = ea[eg * ED_DIM + kl - 1];
        sA[r * LDH + kl] = __float2half_rn(v);
    }
    if (tid < 128) sBIAS[tid] = be1[tid];
    BCOPY_ASYNC(sb1_u, 3);                 // prefetch We2 -> buf1
    CP_WAIT1();                            // chunk2 ready
    __syncthreads();
    MMA_SWEEP(sa_u, sb0_u, 2)              // GEMM1 tail
    __syncthreads();

    // ======== Epilogue 1: m1 = silu(acc + be1) -> sA, reset acc ========
#pragma unroll
    for (int mt = 0; mt < 2; mt++) {
        const int r0 = rb + mt * 16 + g;
#pragma unroll
        for (int nt = 0; nt < 8; nt++) {
            const int col = cb + nt * 8 + 2 * c;
            float* a4 = acc[mt][nt];
            *(__half2*)(sA + r0 * LDH + col) =
                __floats2half2_rn(silu_f(a4[0] + sBIAS[col]), silu_f(a4[1] + sBIAS[col + 1]));
            *(__half2*)(sA + (r0 + 8) * LDH + col) =
                __floats2half2_rn(silu_f(a4[2] + sBIAS[col]), silu_f(a4[3] + sBIAS[col + 1]));
            a4[0] = a4[1] = a4[2] = a4[3] = 0.f;
        }
    }
    BCOPY_ASYNC(sb0_u, 4);                 // prefetch Wx1 -> buf0 (buf0 free)
    CP_WAIT1();                            // We2 ready
    __syncthreads();
    if (tid < 128) sBIAS[tid] = be2[tid];  // overwrite after epi1 readers passed barrier
    MMA_SWEEP(sa_u, sb1_u, 8)              // GEMM2
    __syncthreads();

    // ==== Epilogue 2: m_ij = silu(acc+be2); float4 RED to g_msg; -> sA ====
#pragma unroll
    for (int mt = 0; mt < 2; mt++) {
        const int r0 = rb + mt * 16 + g;
        const int r1 = r0 + 8;
        const int dn0 = sDST[r0], dn1 = sDST[r1];
        const bool v0 = (base + r0) < E_, v1 = (base + r1) < E_;
#pragma unroll
        for (int nt = 0; nt < 8; nt++) {
            const int col = cb + nt * 8 + 2 * c;
            float* a4 = acc[mt][nt];
            const float m00 = silu_f(a4[0] + sBIAS[col]);
            const float m01 = silu_f(a4[1] + sBIAS[col + 1]);
            const float m10 = silu_f(a4[2] + sBIAS[col]);
            const float m11 = silu_f(a4[3] + sBIAS[col + 1]);
            const float s00 = __shfl_xor_sync(0xffffffffu, m00, 1);
            const float s01 = __shfl_xor_sync(0xffffffffu, m01, 1);
            const float s10 = __shfl_xor_sync(0xffffffffu, m10, 1);
            const float s11 = __shfl_xor_sync(0xffffffffu, m11, 1);
            if ((c & 1) == 0) {
                if (v0) {
                    float4 f4 = make_float4(m00, m01, s00, s01);
                    atomicAdd((float4*)(g_msg + (long)dn0 * H_DIM + col), f4);
                }
            } else {
                if (v1) {
                    float4 f4 = make_float4(s10, s11, m10, m11);
                    atomicAdd((float4*)(g_msg + (long)dn1 * H_DIM + col - 2), f4);
                }
            }
            *(__half2*)(sA + r0 * LDH + col) = __floats2half2_rn(m00, m01);
            *(__half2*)(sA + r1 * LDH + col) = __floats2half2_rn(m10, m11);
            a4[0] = a4[1] = a4[2] = a4[3] = 0.f;
        }
    }
    CP_WAIT0();                            // Wx1 ready
    __syncthreads();
    if (tid < 128) { sBIAS[tid] = bx1[tid]; sWX2[tid] = Wx2[tid]; }
    MMA_SWEEP(sa_u, sb0_u, 8)              // GEMM3
    __syncthreads();

    // ===== Epilogue 3: silu, dot with Wx2, reduce, tanh, coord scatter =====
    {
        float p[4] = {0.f, 0.f, 0.f, 0.f};
#pragma unroll
        for (int mt = 0; mt < 2; mt++) {
#pragma unroll
            for (int nt = 0; nt < 8; nt++) {
                const int col = cb + nt * 8 + 2 * c;
                const float w0 = sWX2[col], w1 = sWX2[col + 1];
                float* a4 = acc[mt][nt];
                p[mt * 2 + 0] += silu_f(a4[0] + sBIAS[col]) * w0 + silu_f(a4[1] + sBIAS[col + 1]) * w1;
                p[mt * 2 + 1] += silu_f(a4[2] + sBIAS[col]) * w0 + silu_f(a4[3] + sBIAS[col + 1]) * w1;
            }
        }
#pragma unroll
        for (int off = 1; off <= 2; off <<= 1) {
#pragma unroll
            for (int j = 0; j < 4; j++) p[j] += __shfl_xor_sync(0xffffffffu, p[j], off);
        }
        if (c == 0) {
#pragma unroll
            for (int mt = 0; mt < 2; mt++) {
                sPART[(rb + mt * 16 + g) + warpN * 128] = p[mt * 2 + 0];
                sPART[(rb + mt * 16 + g + 8) + warpN * 128] = p[mt * 2 + 1];
            }
        }
    }
    __syncthreads();
    if (tid < 128) {
        const long eg = base + tid;
        if (eg < E_) {
            const float w = tanhf(sPART[tid] + sPART[tid + 128] + bx2[0]);
            const int dn = sDST[tid];
            atomicAdd(&g_coord[dn * 3 + 0], sDIFF[tid * 3 + 0] * w);
            atomicAdd(&g_coord[dn * 3 + 1], sDIFF[tid * 3 + 1] * w);
            atomicAdd(&g_coord[dn * 3 + 2], sDIFF[tid * 3 + 2] * w);
        }
    }
}

// ---------------------------------------------------------------------------
// Node kernel (fp32, ~70us)
// ---------------------------------------------------------------------------
#define TILE 64
#define MID_LD 132
#define NIN_LD 260

template <int K, bool DO_SILU>
__device__ __forceinline__ void tile_gemm(const float* __restrict__ sA, int lda,
                                          const float* __restrict__ W,
                                          const float* __restrict__ bias,
                                          float* __restrict__ sOut, int ldo,
                                          int tid) {
    const int warp = tid >> 5;
    const int lane = tid & 31;
    const int r0 = warp * 8;
    const int col0 = lane * 4;

    float acc[8][4];
#pragma unroll
    for (int i = 0; i < 8; i++) {
        acc[i][0] = 0.f; acc[i][1] = 0.f; acc[i][2] = 0.f; acc[i][3] = 0.f;
    }
#pragma unroll 4
    for (int k = 0; k < K; k += 4) {
        const float4 w0 = *(const float4*)(W + (k + 0) * H_DIM + col0);
        const float4 w1 = *(const float4*)(W + (k + 1) * H_DIM + col0);
        const float4 w2 = *(const float4*)(W + (k + 2) * H_DIM + col0);
        const float4 w3 = *(const float4*)(W + (k + 3) * H_DIM + col0);
#pragma unroll
        for (int i = 0; i < 8; i++) {
            const float4 a = *(const float4*)(sA + (r0 + i) * lda + k);
            acc[i][0] = fmaf(a.x, w0.x, fmaf(a.y, w1.x, fmaf(a.z, w2.x, fmaf(a.w, w3.x, acc[i][0]))));
            acc[i][1] = fmaf(a.x, w0.y, fmaf(a.y, w1.y, fmaf(a.z, w2.y, fmaf(a.w, w3.y, acc[i][1]))));
            acc[i][2] = fmaf(a.x, w0.z, fmaf(a.y, w1.z, fmaf(a.z, w2.z, fmaf(a.w, w3.z, acc[i][2]))));
            acc[i][3] = fmaf(a.x, w0.w, fmaf(a.y, w1.w, fmaf(a.z, w2.w, fmaf(a.w, w3.w, acc[i][3]))));
        }
    }
    const float4 b = *(const float4*)(bias + col0);
#pragma unroll
    for (int i = 0; i < 8; i++) {
        float4 o;
        o.x = acc[i][0] + b.x; o.y = acc[i][1] + b.y;
        o.z = acc[i][2] + b.z; o.w = acc[i][3] + b.w;
        if (DO_SILU) {
            o.x = silu_f(o.x); o.y = silu_f(o.y);
            o.z = silu_f(o.z); o.w = silu_f(o.w);
        }
        *(float4*)(sOut + (r0 + i) * ldo + col0) = o;
    }
}

__global__ void __launch_bounds__(THREADS, 1)
egnn_node(const float* __restrict__ h, const float* __restrict__ x,
          const int* __restrict__ fixedm,
          const float* __restrict__ Wh1, const float* __restrict__ bh1,
          const float* __restrict__ Wh2, const float* __restrict__ bh2,
          float* __restrict__ out_h, float* __restrict__ out_x, int N_) {
    extern __shared__ float sm[];
    float* s_in = sm;
    float* s_u  = s_in + TILE * NIN_LD;

    const int tid = threadIdx.x;
    const int warp = tid >> 5;
    const int lane = tid & 31;
    const int nBase = blockIdx.x * TILE;

#pragma unroll
    for (int i = 0; i < 8; i++) {
        const int ln = warp * 8 + i;
        const int node = nBase + ln;
        float* row = s_in + ln * NIN_LD;
        if (node < N_) {
            *(float4*)(row + lane * 4) = *(const float4*)(h + (long)node * H_DIM + lane * 4);
            *(float4*)(row + 128 + lane * 4) = *(const float4*)(g_msg + (long)node * H_DIM + lane * 4);
        } else {
            *(float4*)(row + lane * 4) = make_float4(0.f, 0.f, 0.f, 0.f);
            *(float4*)(row + 128 + lane * 4) = make_float4(0.f, 0.f, 0.f, 0.f);
        }
    }
    __syncthreads();

    tile_gemm<2 * H_DIM, true>(s_in, NIN_LD, Wh1, bh1, s_u, MID_LD, tid);
    __syncthreads();
    tile_gemm<H_DIM, false>(s_u, MID_LD, Wh2, bh2, s_in, MID_LD, tid);
    __syncthreads();

#pragma unroll
    for (int i = 0; i < 8; i++) {
        const int ln = warp * 8 + i;
        const int node = nBase + ln;
        if (node < N_) {
            float4 o = *(const float4*)(s_in + ln * MID_LD + lane * 4);
            const float4 hh = *(const float4*)(h + (long)node * H_DIM + lane * 4);
            o.x += hh.x; o.y += hh.y; o.z += hh.z; o.w += hh.w;
            *(float4*)(out_h + (long)node * H_DIM + lane * 4) = o;
        }
    }
    if (tid < TILE * 3) {
        const int li = tid / 3;
        const int c = tid - li * 3;
        const int node = nBase + li;
        if (node < N_) {
            const float add = fixedm[node] ? 0.f : g_coord[node * 3 + c];
            out_x[node * 3 + c] = x[node * 3 + c] + add;
        }
    }
}

// ---------------------------------------------------------------------------
extern "C" void kernel_launch(void* const* d_in, const int* in_sizes, int n_in,
                              void* d_out, int out_size) {
    const float* h   = (const float*)d_in[0];
    const float* x   = (const float*)d_in[1];
    const int* ei    = (const int*)d_in[2];
    const float* ea  = (const float*)d_in[3];
    const int* fixedm = (const int*)d_in[4];
    const float* We1 = (const float*)d_in[5];
    const float* be1 = (const float*)d_in[6];
    const float* We2 = (const float*)d_in[7];
    const float* be2 = (const float*)d_in[8];
    const float* Wx1 = (const float*)d_in[9];
    const float* bx1 = (const float*)d_in[10];
    const float* Wx2 = (const float*)d_in[11];
    const float* bx2 = (const float*)d_in[12];
    const float* Wh1 = (const float*)d_in[13];
    const float* bh1 = (const float*)d_in[14];
    const float* Wh2 = (const float*)d_in[15];
    const float* bh2 = (const float*)d_in[16];

    const int N_ = in_sizes[0] / H_DIM;
    const int E_ = in_sizes[3] / ED_DIM;

    float* out_h = (float*)d_out;
    float* out_x = out_h + (long)N_ * H_DIM;

    void* pmsg = nullptr; void* pcoord = nullptr;
    cudaGetSymbolAddress(&pmsg, g_msg);
    cudaGetSymbolAddress(&pcoord, g_coord);
    cudaMemsetAsync(pmsg, 0, (size_t)N_ * H_DIM * sizeof(float));
    cudaMemsetAsync(pcoord, 0, (size_t)N_ * 3 * sizeof(float));

    prep_w<<<(5 * 128 * LDH + 255) / 256, 256>>>(We1, We2, Wx1);

    cudaFuncSetAttribute(egnn_edge_mma, cudaFuncAttributeMaxDynamicSharedMemorySize, SMEM_BYTES);
    const int eBlocks = (E_ + ETILE - 1) / ETILE;
    egnn_edge_mma<<<eBlocks, THREADS, SMEM_BYTES>>>(h, x, ei, ea, be1, be2, bx1,
                                                    Wx2, bx2, E_);

    const int nodeSmem = (TILE * NIN_LD + TILE * MID_LD) * 4;
    cudaFuncSetAttribute(egnn_node, cudaFuncAttributeMaxDynamicSharedMemorySize, nodeSmem);
    const int nBlocks = (N_ + TILE - 1) / TILE;
    egnn_node<<<nBlocks, THREADS, nodeSmem>>>(h, x, fixedm, Wh1, bh1, Wh2, bh2,
                                              out_h, out_x, N_);

    // cycle length 4 kernels -> ncu's profiled launch (#10) = egnn_edge_mma
    dummy_k<<<1, 32>>>();
}

// round 8
// speedup vs baseline: 5.3797x; 1.1185x over previous
#include <cuda_runtime.h>
#include <cuda_fp16.h>
#include <math.h>
#include <stdint.h>

#define H_DIM 128
#define ED_DIM 16
#define ETILE 128
#define THREADS 256
#define MAX_N 20000
#define LDH 136            // half-element pitch; 272B rows -> ldmatrix conflict-free

// ---------------- device scratch ----------------
__device__ float g_msg[MAX_N * H_DIM];
__device__ float g_coord[MAX_N * 3];
// fp16 transposed weight images Wt[n][k], 8 chunks of [128][LDH]:
// 0,1,2: We1^T  3: We2^T  4: Wx1^T  5,6: Wh1^T  7: Wh2^T
__device__ __half g_B[8 * 128 * LDH];

// silu via tanh.approx: 1 MUFU + 2 FMA
__device__ __forceinline__ float silu_t(float v) {
    float t;
    asm("tanh.approx.f32 %0, %1;" : "=f"(t) : "f"(v * 0.5f));
    const float a = 0.5f * v;
    return fmaf(a, t, a);
}

// ---------------- weight prep ----------------
__global__ void prep_w(const float* __restrict__ We1, const float* __restrict__ We2,
                       const float* __restrict__ Wx1, const float* __restrict__ Wh1,
                       const float* __restrict__ Wh2) {
    const int idx = blockIdx.x * 256 + threadIdx.x;
    if (idx >= 8 * 128 * LDH) return;
    const int chunk = idx / (128 * LDH);
    const int rem = idx % (128 * LDH);
    const int n = rem / LDH, k = rem % LDH;
    float v = 0.f;
    if (chunk == 0)      { if (k < 128) v = We1[k * 128 + n]; }
    else if (chunk == 1) { if (k < 128) v = We1[(128 + k) * 128 + n]; }
    else if (chunk == 2) { if (k <= 16) v = We1[(256 + k) * 128 + n]; }
    else if (chunk == 3) { if (k < 128) v = We2[k * 128 + n]; }
    else if (chunk == 4) { if (k < 128) v = Wx1[k * 128 + n]; }
    else if (chunk == 5) { if (k < 128) v = Wh1[k * 128 + n]; }
    else if (chunk == 6) { if (k < 128) v = Wh1[(128 + k) * 128 + n]; }
    else                 { if (k < 128) v = Wh2[k * 128 + n]; }
    g_B[idx] = __float2half_rn(v);
}

// ---------------- mma / ldmatrix / cp.async helpers ----------------
__device__ __forceinline__ void mma_f16(float* d, const uint32_t* a, const uint32_t* b) {
    asm volatile(
        "mma.sync.aligned.m16n8k16.row.col.f32.f16.f16.f32 "
        "{%0,%1,%2,%3}, {%4,%5,%6,%7}, {%8,%9}, {%0,%1,%2,%3};"
        : "+f"(d[0]), "+f"(d[1]), "+f"(d[2]), "+f"(d[3])
        : "r"(a[0]), "r"(a[1]), "r"(a[2]), "r"(a[3]), "r"(b[0]), "r"(b[1]));
}
__device__ __forceinline__ void ldsm_x4(uint32_t& r0, uint32_t& r1, uint32_t& r2,
                                        uint32_t& r3, uint32_t saddr) {
    asm volatile("ldmatrix.sync.aligned.m8n8.x4.shared.b16 {%0,%1,%2,%3}, [%4];"
                 : "=r"(r0), "=r"(r1), "=r"(r2), "=r"(r3) : "r"(saddr));
}
__device__ __forceinline__ void cp16(uint32_t saddr, const void* gptr) {
    asm volatile("cp.async.cg.shared.global [%0], [%1], 16;"
                 :: "r"(saddr), "l"(gptr));
}
#define CP_COMMIT() asm volatile("cp.async.commit_group;" ::: "memory")
#define CP_WAIT1()  asm volatile("cp.async.wait_group 1;" ::: "memory")
#define CP_WAIT0()  asm volatile("cp.async.wait_group 0;" ::: "memory")

#define BCOPY_ASYNC(DSTU32, CHUNK)                                              \
    do {                                                                        \
        const char* gsrc = (const char*)(g_B + (CHUNK) * 128 * LDH);            \
        for (int i = tid * 16; i < 128 * LDH * 2; i += THREADS * 16)            \
            cp16((DSTU32) + i, gsrc + i);                                       \
        CP_COMMIT();                                                            \
    } while (0)

// smem layout (byte offsets)
#define OFF_A    0                 // half[128*LDH] = 34816 B
#define OFF_B0   34816
#define OFF_B1   69632
#define OFF_BIAS 104448            // float[128]
#define OFF_WX2  104960            // float[128]
#define OFF_DIFF 105472            // float[384]
#define OFF_DST  107008            // int[128]
#define OFF_PART 107520            // float[256]
#define SMEM_BYTES 108544

#define MMA_SWEEP(SA_U32, SB_U32, NST)                                          \
    for (int s = 0; s < (NST); s++) {                                           \
        const int k0 = s * 16;                                                  \
        uint32_t a[2][4], b[8][2];                                              \
        _Pragma("unroll")                                                       \
        for (int mt = 0; mt < 2; mt++)                                          \
            ldsm_x4(a[mt][0], a[mt][1], a[mt][2], a[mt][3],                     \
                    (SA_U32) + (uint32_t)(((rb + mt * 16 + rA) * LDH + k0 + kA) * 2)); \
        _Pragma("unroll")                                                       \
        for (int ntp = 0; ntp < 8; ntp += 2)                                    \
            ldsm_x4(b[ntp][0], b[ntp][1], b[ntp + 1][0], b[ntp + 1][1],         \
                    (SB_U32) + (uint32_t)(((nB + ntp * 8) * LDH + k0 + kB) * 2)); \
        _Pragma("unroll")                                                       \
        for (int mt = 0; mt < 2; mt++)                                          \
            _Pragma("unroll")                                                   \
            for (int nt = 0; nt < 8; nt++) mma_f16(acc[mt][nt], a[mt], b[nt]);  \
    }

// ---------------------------------------------------------------------------
// Edge kernel
// ---------------------------------------------------------------------------
__global__ void __launch_bounds__(THREADS, 2)
egnn_edge_mma(const float* __restrict__ h, const float* __restrict__ x,
              const int* __restrict__ ei, const float* __restrict__ ea,
              const float* __restrict__ be1, const float* __restrict__ be2,
              const float* __restrict__ bx1, const float* __restrict__ Wx2,
              const float* __restrict__ bx2, int E_) {
    extern __shared__ char smraw[];
    __half* sA   = (__half*)(smraw + OFF_A);
    float* sBIAS = (float*)(smraw + OFF_BIAS);
    float* sWX2  = (float*)(smraw + OFF_WX2);
    float* sDIFF = (float*)(smraw + OFF_DIFF);
    int*   sDST  = (int*)(smraw + OFF_DST);
    float* sPART = (float*)(smraw + OFF_PART);

    const int tid = threadIdx.x, warp = tid >> 5, lane = tid & 31;
    const int g = lane >> 2, c = lane & 3;
    const int warpM = warp >> 1, warpN = warp & 1;
    const int rb = warpM * 32, cb = warpN * 64;
    const long base = (long)blockIdx.x * ETILE;

    const int rA = (lane & 7) + ((lane >> 3) & 1) * 8;
    const int kA = ((lane >> 4) & 1) * 8;
    const int nB = cb + ((lane >> 4) & 1) * 8 + (lane & 7);
    const int kB = ((lane >> 3) & 1) * 8;
    const uint32_t smem_u = (uint32_t)__cvta_generic_to_shared(smraw);
    const uint32_t sa_u = smem_u + OFF_A;
    const uint32_t sb0_u = smem_u + OFF_B0;
    const uint32_t sb1_u = smem_u + OFF_B1;

    float acc[2][8][4];
#pragma unroll
    for (int mt = 0; mt < 2; mt++)
#pragma unroll
        for (int nt = 0; nt < 8; nt++)
#pragma unroll
            for (int j = 0; j < 4; j++) acc[mt][nt][j] = 0.f;

    BCOPY_ASYNC(sb0_u, 0);

    // ---- gather A chunk0 (h[src]) + edge meta
#pragma unroll
    for (int i = 0; i < 16; i++) {
        const int r = warp * 16 + i;
        const long eg = base + r;
        const int nd = (eg < E_) ? ei[eg] : 0;
        const float4 v = *(const float4*)(h + (long)nd * H_DIM + lane * 4);
        __half2* dstp = (__half2*)(sA + r * LDH + lane * 4);
        dstp[0] = __floats2half2_rn(v.x, v.y);
        dstp[1] = __floats2half2_rn(v.z, v.w);
        if (lane == 0) {
            const int dn = (eg < E_) ? ei[(long)E_ + eg] : 0;
            sDST[r] = dn;
            const float dx = x[nd * 3 + 0] - x[dn * 3 + 0];
            const float dy = x[nd * 3 + 1] - x[dn * 3 + 1];
            const float dz = x[nd * 3 + 2] - x[dn * 3 + 2];
            sDIFF[r * 3 + 0] = dx; sDIFF[r * 3 + 1] = dy; sDIFF[r * 3 + 2] = dz;
            sPART[r] = (dx * dx + dy * dy + dz * dz) * 0.01f;
        }
    }
    BCOPY_ASYNC(sb1_u, 1);
    CP_WAIT1();
    __syncthreads();
    MMA_SWEEP(sa_u, sb0_u, 8)              // GEMM1 chunk0
    __syncthreads();

    // ---- gather A chunk1 (h[dst])
#pragma unroll
    for (int i = 0; i < 16; i++) {
        const int r = warp * 16 + i;
        const long eg = base + r;
        const int nd = (eg < E_) ? ei[(long)E_ + eg] : 0;
        const float4 v = *(const float4*)(h + (long)nd * H_DIM + lane * 4);
        __half2* dstp = (__half2*)(sA + r * LDH + lane * 4);
        dstp[0] = __floats2half2_rn(v.x, v.y);
        dstp[1] = __floats2half2_rn(v.z, v.w);
    }
    BCOPY_ASYNC(sb0_u, 2);
    CP_WAIT1();
    __syncthreads();
    MMA_SWEEP(sa_u, sb1_u, 8)              // GEMM1 chunk1
    __syncthreads();

    // ---- A tail chunk
    for (int idx = tid; idx < 128 * 32; idx += THREADS) {
        const int r = idx >> 5, kl = idx & 31;
        const long eg = base + r;
        float v = 0.f;
        if (kl == 0) v = sPART[r];
        else if (kl <= 16 && eg < E_) v = ea[eg * ED_DIM + kl - 1];
        sA[r * LDH + kl] = __float2half_rn(v);
    }
    if (tid < 128) sBIAS[tid] = be1[tid];
    BCOPY_ASYNC(sb1_u, 3);
    CP_WAIT1();
    __syncthreads();
    MMA_SWEEP(sa_u, sb0_u, 2)              // GEMM1 tail
    __syncthreads();

    // ======== Epilogue 1 ========
#pragma unroll
    for (int mt = 0; mt < 2; mt++) {
        const int r0 = rb + mt * 16 + g;
#pragma unroll
        for (int nt = 0; nt < 8; nt++) {
            const int col = cb + nt * 8 + 2 * c;
            float* a4 = acc[mt][nt];
            *(__half2*)(sA + r0 * LDH + col) =
                __floats2half2_rn(silu_t(a4[0] + sBIAS[col]), silu_t(a4[1] + sBIAS[col + 1]));
            *(__half2*)(sA + (r0 + 8) * LDH + col) =
                __floats2half2_rn(silu_t(a4[2] + sBIAS[col]), silu_t(a4[3] + sBIAS[col + 1]));
            a4[0] = a4[1] = a4[2] = a4[3] = 0.f;
        }
    }
    BCOPY_ASYNC(sb0_u, 4);
    CP_WAIT1();
    __syncthreads();
    if (tid < 128) sBIAS[tid] = be2[tid];
    MMA_SWEEP(sa_u, sb1_u, 8)              // GEMM2
    __syncthreads();

    // ==== Epilogue 2: m_ij; float4 RED to g_msg; -> sA ====
#pragma unroll
    for (int mt = 0; mt < 2; mt++) {
        const int r0 = rb + mt * 16 + g;
        const int r1 = r0 + 8;
        const int dn0 = sDST[r0], dn1 = sDST[r1];
        const bool v0 = (base + r0) < E_, v1 = (base + r1) < E_;
#pragma unroll
        for (int nt = 0; nt < 8; nt++) {
            const int col = cb + nt * 8 + 2 * c;
            float* a4 = acc[mt][nt];
            const float m00 = silu_t(a4[0] + sBIAS[col]);
            const float m01 = silu_t(a4[1] + sBIAS[col + 1]);
            const float m10 = silu_t(a4[2] + sBIAS[col]);
            const float m11 = silu_t(a4[3] + sBIAS[col + 1]);
            const float s00 = __shfl_xor_sync(0xffffffffu, m00, 1);
            const float s01 = __shfl_xor_sync(0xffffffffu, m01, 1);
            const float s10 = __shfl_xor_sync(0xffffffffu, m10, 1);
            const float s11 = __shfl_xor_sync(0xffffffffu, m11, 1);
            if ((c & 1) == 0) {
                if (v0) {
                    float4 f4 = make_float4(m00, m01, s00, s01);
                    atomicAdd((float4*)(g_msg + (long)dn0 * H_DIM + col), f4);
                }
            } else {
                if (v1) {
                    float4 f4 = make_float4(s10, s11, m10, m11);
                    atomicAdd((float4*)(g_msg + (long)dn1 * H_DIM + col - 2), f4);
                }
            }
            *(__half2*)(sA + r0 * LDH + col) = __floats2half2_rn(m00, m01);
            *(__half2*)(sA + r1 * LDH + col) = __floats2half2_rn(m10, m11);
            a4[0] = a4[1] = a4[2] = a4[3] = 0.f;
        }
    }
    CP_WAIT0();
    __syncthreads();
    if (tid < 128) { sBIAS[tid] = bx1[tid]; sWX2[tid] = Wx2[tid]; }
    MMA_SWEEP(sa_u, sb0_u, 8)              // GEMM3
    __syncthreads();

    // ===== Epilogue 3 =====
    {
        float p[4] = {0.f, 0.f, 0.f, 0.f};
#pragma unroll
        for (int mt = 0; mt < 2; mt++) {
#pragma unroll
            for (int nt = 0; nt < 8; nt++) {
                const int col = cb + nt * 8 + 2 * c;
                const float w0 = sWX2[col], w1 = sWX2[col + 1];
                float* a4 = acc[mt][nt];
                p[mt * 2 + 0] += silu_t(a4[0] + sBIAS[col]) * w0 + silu_t(a4[1] + sBIAS[col + 1]) * w1;
                p[mt * 2 + 1] += silu_t(a4[2] + sBIAS[col]) * w0 + silu_t(a4[3] + sBIAS[col + 1]) * w1;
            }
        }
#pragma unroll
        for (int off = 1; off <= 2; off <<= 1) {
#pragma unroll
            for (int j = 0; j < 4; j++) p[j] += __shfl_xor_sync(0xffffffffu, p[j], off);
        }
        if (c == 0) {
#pragma unroll
            for (int mt = 0; mt < 2; mt++) {
                sPART[(rb + mt * 16 + g) + warpN * 128] = p[mt * 2 + 0];
                sPART[(rb + mt * 16 + g + 8) + warpN * 128] = p[mt * 2 + 1];
            }
        }
    }
    __syncthreads();
    if (tid < 128) {
        const long eg = base + tid;
        if (eg < E_) {
            const float w = tanhf(sPART[tid] + sPART[tid + 128] + bx2[0]);
            const int dn = sDST[tid];
            atomicAdd(&g_coord[dn * 3 + 0], sDIFF[tid * 3 + 0] * w);
            atomicAdd(&g_coord[dn * 3 + 1], sDIFF[tid * 3 + 1] * w);
            atomicAdd(&g_coord[dn * 3 + 2], sDIFF[tid * 3 + 2] * w);
        }
    }
}

// ---------------------------------------------------------------------------
// Node kernel: fp16 mma, same machinery. h_new = h + silu([h,msg]@Wh1+bh1)@Wh2+bh2
// ---------------------------------------------------------------------------
__global__ void __launch_bounds__(THREADS, 2)
egnn_node_mma(const float* __restrict__ h, const float* __restrict__ x,
              const int* __restrict__ fixedm,
              const float* __restrict__ bh1, const float* __restrict__ bh2,
              float* __restrict__ out_h, float* __restrict__ out_x, int N_) {
    extern __shared__ char smraw[];
    __half* sA   = (__half*)(smraw + OFF_A);
    float* sBIAS = (float*)(smraw + OFF_BIAS);
    float* sB2   = (float*)(smraw + OFF_WX2);

    const int tid = threadIdx.x, warp = tid >> 5, lane = tid & 31;
    const int g = lane >> 2, c = lane & 3;
    const int warpM = warp >> 1, warpN = warp & 1;
    const int rb = warpM * 32, cb = warpN * 64;
    const int base = blockIdx.x * ETILE;

    const int rA = (lane & 7) + ((lane >> 3) & 1) * 8;
    const int kA = ((lane >> 4) & 1) * 8;
    const int nB = cb + ((lane >> 4) & 1) * 8 + (lane & 7);
    const int kB = ((lane >> 3) & 1) * 8;
    const uint32_t smem_u = (uint32_t)__cvta_generic_to_shared(smraw);
    const uint32_t sa_u = smem_u + OFF_A;
    const uint32_t sb0_u = smem_u + OFF_B0;
    const uint32_t sb1_u = smem_u + OFF_B1;

    float acc[2][8][4];
#pragma unroll
    for (int mt = 0; mt < 2; mt++)
#pragma unroll
        for (int nt = 0; nt < 8; nt++)
#pragma unroll
            for (int j = 0; j < 4; j++) acc[mt][nt][j] = 0.f;

    BCOPY_ASYNC(sb0_u, 5);
    if (tid < 128) { sBIAS[tid] = bh1[tid]; sB2[tid] = bh2[tid]; }

    // ---- A = h rows (coalesced)
#pragma unroll
    for (int i = 0; i < 16; i++) {
        const int r = warp * 16 + i;
        const int node = base + r;
        float4 v = make_float4(0.f, 0.f, 0.f, 0.f);
        if (node < N_) v = *(const float4*)(h + (long)node * H_DIM + lane * 4);
        __half2* dstp = (__half2*)(sA + r * LDH + lane * 4);
        dstp[0] = __floats2half2_rn(v.x, v.y);
        dstp[1] = __floats2half2_rn(v.z, v.w);
    }
    BCOPY_ASYNC(sb1_u, 6);
    CP_WAIT1();
    __syncthreads();
    MMA_SWEEP(sa_u, sb0_u, 8)              // h @ Wh1[0:128]
    __syncthreads();

    // ---- A = msg rows
#pragma unroll
    for (int i = 0; i < 16; i++) {
        const int r = warp * 16 + i;
        const int node = base + r;
        float4 v = make_float4(0.f, 0.f, 0.f, 0.f);
        if (node < N_) v = *(const float4*)(g_msg + (long)node * H_DIM + lane * 4);
        __half2* dstp = (__half2*)(sA + r * LDH + lane * 4);
        dstp[0] = __floats2half2_rn(v.x, v.y);
        dstp[1] = __floats2half2_rn(v.z, v.w);
    }
    BCOPY_ASYNC(sb0_u, 7);
    CP_WAIT1();
    __syncthreads();
    MMA_SWEEP(sa_u, sb1_u, 8)              // msg @ Wh1[128:256]
    __syncthreads();

    // ---- epi1: u = silu(acc + bh1) -> sA, reset acc
#pragma unroll
    for (int mt = 0; mt < 2; mt++) {
        const int r0 = rb + mt * 16 + g;
#pragma unroll
        for (int nt = 0; nt < 8; nt++) {
            const int col = cb + nt * 8 + 2 * c;
            float* a4 = acc[mt][nt];
            *(__half2*)(sA + r0 * LDH + col) =
                __floats2half2_rn(silu_t(a4[0] + sBIAS[col]), silu_t(a4[1] + sBIAS[col + 1]));
            *(__half2*)(sA + (r0 + 8) * LDH + col) =
                __floats2half2_rn(silu_t(a4[2] + sBIAS[col]), silu_t(a4[3] + sBIAS[col + 1]));
            a4[0] = a4[1] = a4[2] = a4[3] = 0.f;
        }
    }
    CP_WAIT0();
    __syncthreads();
    MMA_SWEEP(sa_u, sb0_u, 8)              // u @ Wh2
    // acc is per-thread; no barrier needed before epilogue

    // ---- epi2: out_h = h + acc + bh2
#pragma unroll
    for (int mt = 0; mt < 2; mt++) {
        const int r0 = rb + mt * 16 + g;
        const int r1 = r0 + 8;
        const int n0 = base + r0, n1 = base + r1;
#pragma unroll
        for (int nt = 0; nt < 8; nt++) {
            const int col = cb + nt * 8 + 2 * c;
            float* a4 = acc[mt][nt];
            if (n0 < N_) {
                const float2 hh = *(const float2*)(h + (long)n0 * H_DIM + col);
                float2 o;
                o.x = a4[0] + sB2[col] + hh.x;
                o.y = a4[1] + sB2[col + 1] + hh.y;
                *(float2*)(out_h + (long)n0 * H_DIM + col) = o;
            }
            if (n1 < N_) {
                const float2 hh = *(const float2*)(h + (long)n1 * H_DIM + col);
                float2 o;
                o.x = a4[2] + sB2[col] + hh.x;
                o.y = a4[3] + sB2[col + 1] + hh.y;
                *(float2*)(out_h + (long)n1 * H_DIM + col) = o;
            }
        }
    }
    // ---- x_new
    for (int idx = tid; idx < ETILE * 3; idx += THREADS) {
        const int li = idx / 3, cc = idx - li * 3;
        const int node = base + li;
        if (node < N_) {
            const float add = fixedm[node] ? 0.f : g_coord[node * 3 + cc];
            out_x[node * 3 + cc] = x[node * 3 + cc] + add;
        }
    }
}

// ---------------------------------------------------------------------------
extern "C" void kernel_launch(void* const* d_in, const int* in_sizes, int n_in,
                              void* d_out, int out_size) {
    const float* h   = (const float*)d_in[0];
    const float* x   = (const float*)d_in[1];
    const int* ei    = (const int*)d_in[2];
    const float* ea  = (const float*)d_in[3];
    const int* fixedm = (const int*)d_in[4];
    const float* We1 = (const float*)d_in[5];
    const float* be1 = (const float*)d_in[6];
    const float* We2 = (const float*)d_in[7];
    const float* be2 = (const float*)d_in[8];
    const float* Wx1 = (const float*)d_in[9];
    const float* bx1 = (const float*)d_in[10];
    const float* Wx2 = (const float*)d_in[11];
    const float* bx2 = (const float*)d_in[12];
    const float* Wh1 = (const float*)d_in[13];
    const float* bh1 = (const float*)d_in[14];
    const float* Wh2 = (const float*)d_in[15];
    const float* bh2 = (const float*)d_in[16];

    const int N_ = in_sizes[0] / H_DIM;
    const int E_ = in_sizes[3] / ED_DIM;

    float* out_h = (float*)d_out;
    float* out_x = out_h + (long)N_ * H_DIM;

    void* pmsg = nullptr; void* pcoord = nullptr;
    cudaGetSymbolAddress(&pmsg, g_msg);
    cudaGetSymbolAddress(&pcoord, g_coord);
    cudaMemsetAsync(pmsg, 0, (size_t)N_ * H_DIM * sizeof(float));
    cudaMemsetAsync(pcoord, 0, (size_t)N_ * 3 * sizeof(float));

    prep_w<<<(8 * 128 * LDH + 255) / 256, 256>>>(We1, We2, Wx1, Wh1, Wh2);

    cudaFuncSetAttribute(egnn_edge_mma, cudaFuncAttributeMaxDynamicSharedMemorySize, SMEM_BYTES);
    const int eBlocks = (E_ + ETILE - 1) / ETILE;
    egnn_edge_mma<<<eBlocks, THREADS, SMEM_BYTES>>>(h, x, ei, ea, be1, be2, bx1,
                                                    Wx2, bx2, E_);

    cudaFuncSetAttribute(egnn_node_mma, cudaFuncAttributeMaxDynamicSharedMemorySize, SMEM_BYTES);
    const int nBlocks = (N_ + ETILE - 1) / ETILE;
    egnn_node_mma<<<nBlocks, THREADS, SMEM_BYTES>>>(h, x, fixedm, bh1, bh2,
                                                    out_h, out_x, N_);
}

// round 9
// speedup vs baseline: 6.3677x; 1.1836x over previous
#include <cuda_runtime.h>
#include <cuda_fp16.h>
#include <math.h>
#include <stdint.h>

#define H_DIM 128
#define ED_DIM 16
#define ETILE 128
#define THREADS 256
#define MAX_N 20000
#define MAX_E 640000
#define LDH 136            // half-element pitch; 272B rows -> ldmatrix conflict-free

// ---------------- device scratch ----------------
__device__ float g_msg[MAX_N * H_DIM];
__device__ float g_coord[MAX_N * 3];
__device__ __half g_h16[MAX_N * H_DIM];     // fp16 image of h
__device__ __half g_ea16[MAX_E * ED_DIM];   // fp16 image of edge_attr
// fp16 transposed weight images Wt[n][k], 8 chunks of [128][LDH]:
// 0,1: We1^T k0..255  2: tail (k0..15=ea rows 257..272, k16=dist row 256)
// 3: We2^T  4: Wx1^T  5,6: Wh1^T  7: Wh2^T
__device__ __half g_B[8 * 128 * LDH];

// silu via tanh.approx: 1 MUFU + 2 FMA
__device__ __forceinline__ float silu_t(float v) {
    float t;
    asm("tanh.approx.f32 %0, %1;" : "=f"(t) : "f"(v * 0.5f));
    const float a = 0.5f * v;
    return fmaf(a, t, a);
}

// ---------------- weight prep ----------------
__global__ void prep_w(const float* __restrict__ We1, const float* __restrict__ We2,
                       const float* __restrict__ Wx1, const float* __restrict__ Wh1,
                       const float* __restrict__ Wh2) {
    const int idx = blockIdx.x * 256 + threadIdx.x;
    if (idx >= 8 * 128 * LDH) return;
    const int chunk = idx / (128 * LDH);
    const int rem = idx % (128 * LDH);
    const int n = rem / LDH, k = rem % LDH;
    float v = 0.f;
    if (chunk == 0)      { if (k < 128) v = We1[k * 128 + n]; }
    else if (chunk == 1) { if (k < 128) v = We1[(128 + k) * 128 + n]; }
    else if (chunk == 2) { if (k < 16) v = We1[(257 + k) * 128 + n];
                           else if (k == 16) v = We1[256 * 128 + n]; }
    else if (chunk == 3) { if (k < 128) v = We2[k * 128 + n]; }
    else if (chunk == 4) { if (k < 128) v = Wx1[k * 128 + n]; }
    else if (chunk == 5) { if (k < 128) v = Wh1[k * 128 + n]; }
    else if (chunk == 6) { if (k < 128) v = Wh1[(128 + k) * 128 + n]; }
    else                 { if (k < 128) v = Wh2[k * 128 + n]; }
    g_B[idx] = __float2half_rn(v);
}

// convert h + edge_attr to fp16 images
__global__ void prep_act(const float* __restrict__ h, const float* __restrict__ ea,
                         int nh, int nea) {
    const int idx = blockIdx.x * 256 + threadIdx.x;
    if (idx < nh) g_h16[idx] = __float2half_rn(h[idx]);
    else if (idx < nh + nea) g_ea16[idx - nh] = __float2half_rn(ea[idx - nh]);
}

// ---------------- mma / ldmatrix / cp.async helpers ----------------
__device__ __forceinline__ void mma_f16(float* d, const uint32_t* a, const uint32_t* b) {
    asm volatile(
        "mma.sync.aligned.m16n8k16.row.col.f32.f16.f16.f32 "
        "{%0,%1,%2,%3}, {%4,%5,%6,%7}, {%8,%9}, {%0,%1,%2,%3};"
        : "+f"(d[0]), "+f"(d[1]), "+f"(d[2]), "+f"(d[3])
        : "r"(a[0]), "r"(a[1]), "r"(a[2]), "r"(a[3]), "r"(b[0]), "r"(b[1]));
}
__device__ __forceinline__ void ldsm_x4(uint32_t& r0, uint32_t& r1, uint32_t& r2,
                                        uint32_t& r3, uint32_t saddr) {
    asm volatile("ldmatrix.sync.aligned.m8n8.x4.shared.b16 {%0,%1,%2,%3}, [%4];"
                 : "=r"(r0), "=r"(r1), "=r"(r2), "=r"(r3) : "r"(saddr));
}
__device__ __forceinline__ void cp16(uint32_t saddr, const void* gptr) {
    asm volatile("cp.async.cg.shared.global [%0], [%1], 16;"
                 :: "r"(saddr), "l"(gptr));
}
#define CP_COMMIT() asm volatile("cp.async.commit_group;" ::: "memory")
#define CP_WAIT1()  asm volatile("cp.async.wait_group 1;" ::: "memory")
#define CP_WAIT0()  asm volatile("cp.async.wait_group 0;" ::: "memory")

#define BCOPY_ASYNC(DSTU32, CHUNK)                                              \
    do {                                                                        \
        const char* gsrc = (const char*)(g_B + (CHUNK) * 128 * LDH);            \
        for (int i = tid * 16; i < 128 * LDH * 2; i += THREADS * 16)            \
            cp16((DSTU32) + i, gsrc + i);                                       \
        CP_COMMIT();                                                            \
    } while (0)

// gather 128 rows (256B each) from a half image into sA; 2 threads per row
#define AGATHER_ASYNC(IDXEXPR)                                                  \
    do {                                                                        \
        const int r_ = tid >> 1;                                                \
        const int ho_ = (tid & 1) * 64;                                         \
        const long eg_ = base + r_;                                             \
        const int nd_ = IDXEXPR;                                                \
        const __half* src_ = g_h16 + (long)nd_ * H_DIM + ho_;                   \
        const uint32_t dst_ = sa_u + (uint32_t)(r_ * LDH + ho_) * 2;            \
        _Pragma("unroll")                                                       \
        for (int i_ = 0; i_ < 8; i_++) cp16(dst_ + i_ * 16, src_ + i_ * 8);     \
        CP_COMMIT();                                                            \
    } while (0)

// smem layout (byte offsets)
#define OFF_A    0                 // half[128*LDH] = 34816 B
#define OFF_B0   34816
#define OFF_B1   69632
#define OFF_BIAS 104448            // float[128]
#define OFF_WX2  104960            // float[128]
#define OFF_DIFF 105472            // float[384]
#define OFF_DST  107008            // int[128]
#define OFF_PART 107520            // float[256]
#define SMEM_BYTES 108544

#define MMA_SWEEP(SA_U32, SB_U32, NST)                                          \
    for (int s = 0; s < (NST); s++) {                                           \
        const int k0 = s * 16;                                                  \
        uint32_t a[2][4], b[8][2];                                              \
        _Pragma("unroll")                                                       \
        for (int mt = 0; mt < 2; mt++)                                          \
            ldsm_x4(a[mt][0], a[mt][1], a[mt][2], a[mt][3],                     \
                    (SA_U32) + (uint32_t)(((rb + mt * 16 + rA) * LDH + k0 + kA) * 2)); \
        _Pragma("unroll")                                                       \
        for (int ntp = 0; ntp < 8; ntp += 2)                                    \
            ldsm_x4(b[ntp][0], b[ntp][1], b[ntp + 1][0], b[ntp + 1][1],         \
                    (SB_U32) + (uint32_t)(((nB + ntp * 8) * LDH + k0 + kB) * 2)); \
        _Pragma("unroll")                                                       \
        for (int mt = 0; mt < 2; mt++)                                          \
            _Pragma("unroll")                                                   \
            for (int nt = 0; nt < 8; nt++) mma_f16(acc[mt][nt], a[mt], b[nt]);  \
    }

// ---------------------------------------------------------------------------
// Edge kernel
// ---------------------------------------------------------------------------
__global__ void __launch_bounds__(THREADS, 2)
egnn_edge_mma(const float* __restrict__ x,
              const int* __restrict__ ei,
              const float* __restrict__ be1, const float* __restrict__ be2,
              const float* __restrict__ bx1, const float* __restrict__ Wx2,
              const float* __restrict__ bx2, int E_) {
    extern __shared__ char smraw[];
    __half* sA   = (__half*)(smraw + OFF_A);
    float* sBIAS = (float*)(smraw + OFF_BIAS);
    float* sWX2  = (float*)(smraw + OFF_WX2);
    float* sDIFF = (float*)(smraw + OFF_DIFF);
    int*   sDST  = (int*)(smraw + OFF_DST);
    float* sPART = (float*)(smraw + OFF_PART);

    const int tid = threadIdx.x, warp = tid >> 5, lane = tid & 31;
    const int g = lane >> 2, c = lane & 3;
    const int warpM = warp >> 1, warpN = warp & 1;
    const int rb = warpM * 32, cb = warpN * 64;
    const long base = (long)blockIdx.x * ETILE;

    const int rA = (lane & 7) + ((lane >> 3) & 1) * 8;
    const int kA = ((lane >> 4) & 1) * 8;
    const int nB = cb + ((lane >> 4) & 1) * 8 + (lane & 7);
    const int kB = ((lane >> 3) & 1) * 8;
    const uint32_t smem_u = (uint32_t)__cvta_generic_to_shared(smraw);
    const uint32_t sa_u = smem_u + OFF_A;
    const uint32_t sb0_u = smem_u + OFF_B0;
    const uint32_t sb1_u = smem_u + OFF_B1;

    float acc[2][8][4];
#pragma unroll
    for (int mt = 0; mt < 2; mt++)
#pragma unroll
        for (int nt = 0; nt < 8; nt++)
#pragma unroll
            for (int j = 0; j < 4; j++) acc[mt][nt][j] = 0.f;

    // groups: [A-src], [B0], [B1]
    AGATHER_ASYNC((eg_ < E_) ? ei[eg_] : 0);
    BCOPY_ASYNC(sb0_u, 0);
    BCOPY_ASYNC(sb1_u, 1);

    // meta: one edge per thread (tid < 128)
    if (tid < 128) {
        const int r = tid;
        const long eg = base + r;
        int sn = 0, dn = 0;
        if (eg < E_) { sn = ei[eg]; dn = ei[(long)E_ + eg]; }
        sDST[r] = dn;
        const float dx = x[sn * 3 + 0] - x[dn * 3 + 0];
        const float dy = x[sn * 3 + 1] - x[dn * 3 + 1];
        const float dz = x[sn * 3 + 2] - x[dn * 3 + 2];
        sDIFF[r * 3 + 0] = dx; sDIFF[r * 3 + 1] = dy; sDIFF[r * 3 + 2] = dz;
        sPART[r] = (dx * dx + dy * dy + dz * dz) * 0.01f;
    }
    CP_WAIT1();                            // A-src + B0 ready
    __syncthreads();
    MMA_SWEEP(sa_u, sb0_u, 8)              // GEMM1 chunk0
    __syncthreads();

    // groups: [A-dst], [B2]
    AGATHER_ASYNC((eg_ < E_) ? ei[(long)E_ + eg_] : 0);
    BCOPY_ASYNC(sb0_u, 2);
    CP_WAIT1();                            // B1 + A-dst ready
    __syncthreads();
    MMA_SWEEP(sa_u, sb1_u, 8)              // GEMM1 chunk1
    __syncthreads();

    // tail: ea via cp16 (k0..15), dist scalar (k16); k17..31 garbage x zero-B = 0
    {
        const int r = tid >> 1, seg = tid & 1;
        const long eg = base + r;
        const long ee = (eg < E_) ? eg : 0;
        cp16(sa_u + (uint32_t)(r * LDH) * 2 + seg * 16,
             g_ea16 + ee * ED_DIM + seg * 8);
        CP_COMMIT();                       // group [ea]
    }
    if (tid < 128) {
        sA[tid * LDH + 16] = __float2half_rn(sPART[tid]);
        sBIAS[tid] = be1[tid];
    }
    BCOPY_ASYNC(sb1_u, 3);
    CP_WAIT1();                            // B2 + ea ready
    __syncthreads();
    MMA_SWEEP(sa_u, sb0_u, 2)              // GEMM1 tail
    __syncthreads();

    // ======== Epilogue 1 ========
#pragma unroll
    for (int mt = 0; mt < 2; mt++) {
        const int r0 = rb + mt * 16 + g;
#pragma unroll
        for (int nt = 0; nt < 8; nt++) {
            const int col = cb + nt * 8 + 2 * c;
            float* a4 = acc[mt][nt];
            *(__half2*)(sA + r0 * LDH + col) =
                __floats2half2_rn(silu_t(a4[0] + sBIAS[col]), silu_t(a4[1] + sBIAS[col + 1]));
            *(__half2*)(sA + (r0 + 8) * LDH + col) =
                __floats2half2_rn(silu_t(a4[2] + sBIAS[col]), silu_t(a4[3] + sBIAS[col + 1]));
            a4[0] = a4[1] = a4[2] = a4[3] = 0.f;
        }
    }
    BCOPY_ASYNC(sb0_u, 4);
    CP_WAIT1();                            // B3 ready
    __syncthreads();
    if (tid < 128) sBIAS[tid] = be2[tid];
    MMA_SWEEP(sa_u, sb1_u, 8)              // GEMM2
    __syncthreads();

    // ==== Epilogue 2: m_ij; float4 RED to g_msg; -> sA ====
#pragma unroll
    for (int mt = 0; mt < 2; mt++) {
        const int r0 = rb + mt * 16 + g;
        const int r1 = r0 + 8;
        const int dn0 = sDST[r0], dn1 = sDST[r1];
        const bool v0 = (base + r0) < E_, v1 = (base + r1) < E_;
#pragma unroll
        for (int nt = 0; nt < 8; nt++) {
            const int col = cb + nt * 8 + 2 * c;
            float* a4 = acc[mt][nt];
            const float m00 = silu_t(a4[0] + sBIAS[col]);
            const float m01 = silu_t(a4[1] + sBIAS[col + 1]);
            const float m10 = silu_t(a4[2] + sBIAS[col]);
            const float m11 = silu_t(a4[3] + sBIAS[col + 1]);
            const float s00 = __shfl_xor_sync(0xffffffffu, m00, 1);
            const float s01 = __shfl_xor_sync(0xffffffffu, m01, 1);
            const float s10 = __shfl_xor_sync(0xffffffffu, m10, 1);
            const float s11 = __shfl_xor_sync(0xffffffffu, m11, 1);
            if ((c & 1) == 0) {
                if (v0) {
                    float4 f4 = make_float4(m00, m01, s00, s01);
                    atomicAdd((float4*)(g_msg + (long)dn0 * H_DIM + col), f4);
                }
            } else {
                if (v1) {
                    float4 f4 = make_float4(s10, s11, m10, m11);
                    atomicAdd((float4*)(g_msg + (long)dn1 * H_DIM + col - 2), f4);
                }
            }
            *(__half2*)(sA + r0 * LDH + col) = __floats2half2_rn(m00, m01);
            *(__half2*)(sA + r1 * LDH + col) = __floats2half2_rn(m10, m11);
            a4[0] = a4[1] = a4[2] = a4[3] = 0.f;
        }
    }
    CP_WAIT0();                            // B4 ready
    __syncthreads();
    if (tid < 128) { sBIAS[tid] = bx1[tid]; sWX2[tid] = Wx2[tid]; }
    __syncthreads();                       // publish bx1/Wx2 before epi3 readers
    MMA_SWEEP(sa_u, sb0_u, 8)              // GEMM3
    // ===== Epilogue 3 =====
    {
        float p[4] = {0.f, 0.f, 0.f, 0.f};
#pragma unroll
        for (int mt = 0; mt < 2; mt++) {
#pragma unroll
            for (int nt = 0; nt < 8; nt++) {
                const int col = cb + nt * 8 + 2 * c;
                const float w0 = sWX2[col], w1 = sWX2[col + 1];
                float* a4 = acc[mt][nt];
                p[mt * 2 + 0] += silu_t(a4[0] + sBIAS[col]) * w0 + silu_t(a4[1] + sBIAS[col + 1]) * w1;
                p[mt * 2 + 1] += silu_t(a4[2] + sBIAS[col]) * w0 + silu_t(a4[3] + sBIAS[col + 1]) * w1;
            }
        }
#pragma unroll
        for (int off = 1; off <= 2; off <<= 1) {
#pragma unroll
            for (int j = 0; j < 4; j++) p[j] += __shfl_xor_sync(0xffffffffu, p[j], off);
        }
        if (c == 0) {
#pragma unroll
            for (int mt = 0; mt < 2; mt++) {
                sPART[(rb + mt * 16 + g) + warpN * 128] = p[mt * 2 + 0];
                sPART[(rb + mt * 16 + g + 8) + warpN * 128] = p[mt * 2 + 1];
            }
        }
    }
    __syncthreads();
    if (tid < 128) {
        const long eg = base + tid;
        if (eg < E_) {
            const float w = tanhf(sPART[tid] + sPART[tid + 128] + bx2[0]);
            const int dn = sDST[tid];
            atomicAdd(&g_coord[dn * 3 + 0], sDIFF[tid * 3 + 0] * w);
            atomicAdd(&g_coord[dn * 3 + 1], sDIFF[tid * 3 + 1] * w);
            atomicAdd(&g_coord[dn * 3 + 2], sDIFF[tid * 3 + 2] * w);
        }
    }
}

// ---------------------------------------------------------------------------
// Node kernel: fp16 mma. h_new = h + silu([h,msg]@Wh1+bh1)@Wh2+bh2
// ---------------------------------------------------------------------------
__global__ void __launch_bounds__(THREADS, 2)
egnn_node_mma(const float* __restrict__ h, const float* __restrict__ x,
              const int* __restrict__ fixedm,
              const float* __restrict__ bh1, const float* __restrict__ bh2,
              float* __restrict__ out_h, float* __restrict__ out_x, int N_) {
    extern __shared__ char smraw[];
    __half* sA   = (__half*)(smraw + OFF_A);
    float* sBIAS = (float*)(smraw + OFF_BIAS);
    float* sB2   = (float*)(smraw + OFF_WX2);

    const int tid = threadIdx.x, warp = tid >> 5, lane = tid & 31;
    const int g = lane >> 2, c = lane & 3;
    const int warpM = warp >> 1, warpN = warp & 1;
    const int rb = warpM * 32, cb = warpN * 64;
    const long base = (long)blockIdx.x * ETILE;

    const int rA = (lane & 7) + ((lane >> 3) & 1) * 8;
    const int kA = ((lane >> 4) & 1) * 8;
    const int nB = cb + ((lane >> 4) & 1) * 8 + (lane & 7);
    const int kB = ((lane >> 3) & 1) * 8;
    const uint32_t smem_u = (uint32_t)__cvta_generic_to_shared(smraw);
    const uint32_t sa_u = smem_u + OFF_A;
    const uint32_t sb0_u = smem_u + OFF_B0;
    const uint32_t sb1_u = smem_u + OFF_B1;

    float acc[2][8][4];
#pragma unroll
    for (int mt = 0; mt < 2; mt++)
#pragma unroll
        for (int nt = 0; nt < 8; nt++)
#pragma unroll
            for (int j = 0; j < 4; j++) acc[mt][nt][j] = 0.f;

    // groups: [A-h], [B5], [B6]
    {
        const int r_ = tid >> 1;
        const int ho_ = (tid & 1) * 64;
        long node = base + r_;
        if (node >= N_) node = N_ - 1;
        const __half* src_ = g_h16 + node * H_DIM + ho_;
        const uint32_t dst_ = sa_u + (uint32_t)(r_ * LDH + ho_) * 2;
#pragma unroll
        for (int i_ = 0; i_ < 8; i_++) cp16(dst_ + i_ * 16, src_ + i_ * 8);
        CP_COMMIT();
    }
    BCOPY_ASYNC(sb0_u, 5);
    BCOPY_ASYNC(sb1_u, 6);
    if (tid < 128) { sBIAS[tid] = bh1[tid]; sB2[tid] = bh2[tid]; }
    CP_WAIT1();                            // A-h + B5
    __syncthreads();
    MMA_SWEEP(sa_u, sb0_u, 8)              // h @ Wh1[0:128]
    __syncthreads();

    // ---- A = msg rows (fp32 source -> convert)
#pragma unroll
    for (int i = 0; i < 16; i++) {
        const int r = warp * 16 + i;
        const long node = base + r;
        float4 v = make_float4(0.f, 0.f, 0.f, 0.f);
        if (node < N_) v = *(const float4*)(g_msg + node * H_DIM + lane * 4);
        __half2* dstp = (__half2*)(sA + r * LDH + lane * 4);
        dstp[0] = __floats2half2_rn(v.x, v.y);
        dstp[1] = __floats2half2_rn(v.z, v.w);
    }
    BCOPY_ASYNC(sb0_u, 7);
    CP_WAIT1();                            // B6
    __syncthreads();
    MMA_SWEEP(sa_u, sb1_u, 8)              // msg @ Wh1[128:256]
    __syncthreads();

    // ---- epi1: u = silu(acc + bh1) -> sA, reset acc
#pragma unroll
    for (int mt = 0; mt < 2; mt++) {
        const int r0 = rb + mt * 16 + g;
#pragma unroll
        for (int nt = 0; nt < 8; nt++) {
            const int col = cb + nt * 8 + 2 * c;
            float* a4 = acc[mt][nt];
            *(__half2*)(sA + r0 * LDH + col) =
                __floats2half2_rn(silu_t(a4[0] + sBIAS[col]), silu_t(a4[1] + sBIAS[col + 1]));
            *(__half2*)(sA + (r0 + 8) * LDH + col) =
                __floats2half2_rn(silu_t(a4[2] + sBIAS[col]), silu_t(a4[3] + sBIAS[col + 1]));
            a4[0] = a4[1] = a4[2] = a4[3] = 0.f;
        }
    }
    CP_WAIT0();                            // B7
    __syncthreads();
    MMA_SWEEP(sa_u, sb0_u, 8)              // u @ Wh2

    // ---- epi2: out_h = h + acc + bh2
#pragma unroll
    for (int mt = 0; mt < 2; mt++) {
        const int r0 = rb + mt * 16 + g;
        const int r1 = r0 + 8;
        const long n0 = base + r0, n1 = base + r1;
#pragma unroll
        for (int nt = 0; nt < 8; nt++) {
            const int col = cb + nt * 8 + 2 * c;
            float* a4 = acc[mt][nt];
            if (n0 < N_) {
                const float2 hh = *(const float2*)(h + n0 * H_DIM + col);
                float2 o;
                o.x = a4[0] + sB2[col] + hh.x;
                o.y = a4[1] + sB2[col + 1] + hh.y;
                *(float2*)(out_h + n0 * H_DIM + col) = o;
            }
            if (n1 < N_) {
                const float2 hh = *(const float2*)(h + n1 * H_DIM + col);
                float2 o;
                o.x = a4[2] + sB2[col] + hh.x;
                o.y = a4[3] + sB2[col + 1] + hh.y;
                *(float2*)(out_h + n1 * H_DIM + col) = o;
            }
        }
    }
    // ---- x_new
    for (int idx = tid; idx < ETILE * 3; idx += THREADS) {
        const int li = idx / 3, cc = idx - li * 3;
        const long node = base + li;
        if (node < N_) {
            const float add = fixedm[node] ? 0.f : g_coord[node * 3 + cc];
            out_x[node * 3 + cc] = x[node * 3 + cc] + add;
        }
    }
}

// ---------------------------------------------------------------------------
extern "C" void kernel_launch(void* const* d_in, const int* in_sizes, int n_in,
                              void* d_out, int out_size) {
    const float* h   = (const float*)d_in[0];
    const float* x   = (const float*)d_in[1];
    const int* ei    = (const int*)d_in[2];
    const float* ea  = (const float*)d_in[3];
    const int* fixedm = (const int*)d_in[4];
    const float* We1 = (const float*)d_in[5];
    const float* be1 = (const float*)d_in[6];
    const float* We2 = (const float*)d_in[7];
    const float* be2 = (const float*)d_in[8];
    const float* Wx1 = (const float*)d_in[9];
    const float* bx1 = (const float*)d_in[10];
    const float* Wx2 = (const float*)d_in[11];
    const float* bx2 = (const float*)d_in[12];
    const float* Wh1 = (const float*)d_in[13];
    const float* bh1 = (const float*)d_in[14];
    const float* Wh2 = (const float*)d_in[15];
    const float* bh2 = (const float*)d_in[16];

    const int N_ = in_sizes[0] / H_DIM;
    const int E_ = in_sizes[3] / ED_DIM;

    float* out_h = (float*)d_out;
    float* out_x = out_h + (long)N_ * H_DIM;

    void* pmsg = nullptr; void* pcoord = nullptr;
    cudaGetSymbolAddress(&pmsg, g_msg);
    cudaGetSymbolAddress(&pcoord, g_coord);
    cudaMemsetAsync(pmsg, 0, (size_t)N_ * H_DIM * sizeof(float));
    cudaMemsetAsync(pcoord, 0, (size_t)N_ * 3 * sizeof(float));

    prep_w<<<(8 * 128 * LDH + 255) / 256, 256>>>(We1, We2, Wx1, Wh1, Wh2);
    const int nact = N_ * H_DIM + E_ * ED_DIM;
    prep_act<<<(nact + 255) / 256, 256>>>(h, ea, N_ * H_DIM, E_ * ED_DIM);

    cudaFuncSetAttribute(egnn_edge_mma, cudaFuncAttributeMaxDynamicSharedMemorySize, SMEM_BYTES);
    const int eBlocks = (E_ + ETILE - 1) / ETILE;
    egnn_edge_mma<<<eBlocks, THREADS, SMEM_BYTES>>>(x, ei, be1, be2, bx1,
                                                    Wx2, bx2, E_);

    cudaFuncSetAttribute(egnn_node_mma, cudaFuncAttributeMaxDynamicSharedMemorySize, SMEM_BYTES);
    const int nBlocks = (N_ + ETILE - 1) / ETILE;
    egnn_node_mma<<<nBlocks, THREADS, SMEM_BYTES>>>(h, x, fixedm, bh1, bh2,
                                                    out_h, out_x, N_);
}